// round 8
// baseline (speedup 1.0000x reference)
#include <cuda_runtime.h>
#include <cuda_bf16.h>
#include <cstdint>

#define N_NODES 50000
#define N_EDGES 400000
#define IN_C 32
#define OUT_C 32
#define EDGE_DIM 16
#define HIDDEN 128
#define BN_EPS 1e-5f

#define A_COLS (HIDDEN * IN_C)   // 4096
#define A_U32 (A_COLS / 2)       // 2048 packed u32 per node per plane
#define BN_BLOCKS 232

// GEMM tiling
#define BM 128
#define BK 32
#define NKT (A_COLS / BK)  // 128
#define ASTR 40
#define WSTR 40
#define GEMM_DYN 51200     // dynamic smem: 2x(A_hi+A_lo) + 2x(Wt_hi+Wt_lo)

// abuild
#define ECHUNK 128
#define ABLK 5920          // 40 blocks x 148 SMs, grid-stride over nodes

// ---------------- static device scratch (no allocations allowed) ------------
__device__ uint32_t g_Ah[(size_t)N_NODES * A_U32];     // 410 MB (bf16 hi pairs)
__device__ uint32_t g_Al[(size_t)N_NODES * A_U32];     // 410 MB (bf16 lo pairs)
__device__ uint32_t g_w2h[128 * 512];                  // W2 hi plane [kt][n][kp]
__device__ uint32_t g_w2l[128 * 512];
__device__ float g_xsum[(size_t)N_NODES * IN_C];
__device__ float g_h[(size_t)N_NODES * OUT_C];
__device__ int   g_hist[N_NODES];   // zero at module load; re-zeroed by k_scan
__device__ int   g_off[N_NODES + 1];
__device__ int   g_cursor[N_NODES];
__device__ int   g_perm[N_EDGES];
__device__ double g_psum[BN_BLOCKS][OUT_C];
__device__ double g_psq[BN_BLOCKS][OUT_C];
__device__ float g_scale[OUT_C];
__device__ float g_shift[OUT_C];

// ---------------- helpers ----------------------------------------------------
__device__ __forceinline__ void split_bf(float v, __nv_bfloat16& h,
                                         __nv_bfloat16& l) {
    h = __float2bfloat16_rn(v);
    l = __float2bfloat16_rn(v - __bfloat162float(h));
}

__device__ __forceinline__ uint32_t pack_bf(__nv_bfloat16 a, __nv_bfloat16 b) {
    __nv_bfloat162 p;
    p.x = a; p.y = b;
    return *reinterpret_cast<uint32_t*>(&p);
}

__device__ __forceinline__ uint32_t lds_u32(const __nv_bfloat16* p) {
    return *reinterpret_cast<const uint32_t*>(p);
}

__device__ __forceinline__ void mma16816(float c[4], uint32_t a0, uint32_t a1,
                                         uint32_t a2, uint32_t a3, uint32_t b0,
                                         uint32_t b1) {
    asm volatile(
        "mma.sync.aligned.m16n8k16.row.col.f32.bf16.bf16.f32 "
        "{%0,%1,%2,%3}, {%4,%5,%6,%7}, {%8,%9}, {%0,%1,%2,%3};"
        : "+f"(c[0]), "+f"(c[1]), "+f"(c[2]), "+f"(c[3])
        : "r"(a0), "r"(a1), "r"(a2), "r"(a3), "r"(b0), "r"(b1));
}

// packed f32x2 ops (sm_100+)
__device__ __forceinline__ unsigned long long pack2(float a, float b) {
    unsigned long long r;
    asm("mov.b64 %0, {%1, %2};" : "=l"(r) : "f"(a), "f"(b));
    return r;
}
__device__ __forceinline__ void unpack2(unsigned long long v, float& a, float& b) {
    asm("mov.b64 {%0, %1}, %2;" : "=f"(a), "=f"(b) : "l"(v));
}
__device__ __forceinline__ void fma2(unsigned long long& d, unsigned long long a,
                                     unsigned long long b) {
    asm("fma.rn.f32x2 %0, %1, %2, %0;" : "+l"(d) : "l"(a), "l"(b));
}
__device__ __forceinline__ unsigned long long mul2(unsigned long long a,
                                                   unsigned long long b) {
    unsigned long long r;
    asm("mul.rn.f32x2 %0, %1, %2;" : "=l"(r) : "l"(a), "l"(b));
    return r;
}

// self-detecting edge-index load (int32 vs int64 buffer layout)
__device__ __forceinline__ int detect64(const void* ei) {
    const int* p = (const int*)ei;
    return (p[1] == 0) & (p[3] == 0) & (p[5] == 0) & (p[7] == 0);
}
__device__ __forceinline__ int load_idx(const void* ei, int is64, long long elem) {
    int v = is64 ? (int)((const long long*)ei)[elem] : ((const int*)ei)[elem];
    return min(max(v, 0), N_NODES - 1);
}

// ---------------- launch 1: histogram over dst + W2 pre-split ----------------
__global__ void k_hist(const void* __restrict__ ei, const float* __restrict__ w2) {
    int is64 = detect64(ei);
    for (int i = blockIdx.x * blockDim.x + threadIdx.x; i < N_EDGES;
         i += gridDim.x * blockDim.x) {
        int dst = load_idx(ei, is64, (long long)N_EDGES + i);
        atomicAdd(&g_hist[dst], 1);
    }
    for (int id = blockIdx.x * blockDim.x + threadIdx.x; id < 128 * 512;
         id += gridDim.x * blockDim.x) {
        int kt = id >> 9, r = id & 511;
        int n = r >> 4, kp = r & 15;
        int k0 = kt * 32 + 2 * kp;
        float v0 = w2[(size_t)k0 * 32 + n];
        float v1 = w2[(size_t)(k0 + 1) * 32 + n];
        __nv_bfloat16 h0, l0, h1, l1;
        split_bf(v0, h0, l0);
        split_bf(v1, h1, l1);
        g_w2h[id] = pack_bf(h0, h1);
        g_w2l[id] = pack_bf(l0, l1);
    }
}

// ---------------- launch 2: single-block scan (also re-zeros g_hist) --------
__device__ __forceinline__ int block_excl_scan1024(int v, int* ws) {
    int tid = threadIdx.x;
    int lane = tid & 31, wid = tid >> 5;
    int incl = v;
#pragma unroll
    for (int o = 1; o < 32; o <<= 1) {
        int nv = __shfl_up_sync(0xffffffffu, incl, o);
        if (lane >= o) incl += nv;
    }
    if (lane == 31) ws[wid] = incl;
    __syncthreads();
    if (wid == 0) {
        int wv = ws[lane];
#pragma unroll
        for (int o = 1; o < 32; o <<= 1) {
            int nv = __shfl_up_sync(0xffffffffu, wv, o);
            if (lane >= o) wv += nv;
        }
        ws[lane] = wv;
    }
    __syncthreads();
    int base = (wid > 0) ? ws[wid - 1] : 0;
    return base + incl - v;
}

__global__ void __launch_bounds__(1024) k_scan() {
    __shared__ int ws[32];
    __shared__ int s_carry;
    int tid = threadIdx.x;
    if (tid == 0) s_carry = 0;
    __syncthreads();
    for (int base = 0; base < N_NODES; base += 1024) {
        int idx = base + tid;
        int v = (idx < N_NODES) ? g_hist[idx] : 0;
        int ex = block_excl_scan1024(v, ws);
        int c = s_carry;
        if (idx < N_NODES) {
            g_off[idx] = c + ex;
            g_cursor[idx] = c + ex;
            g_hist[idx] = 0;
        }
        __syncthreads();
        if (tid == 1023) s_carry = c + ex + v;
        __syncthreads();
    }
    if (tid == 0) g_off[N_NODES] = N_EDGES;
}

// ---------------- launch 3: scatter edge ids grouped by dst -----------------
__global__ void k_scatter(const void* __restrict__ ei) {
    int is64 = detect64(ei);
    for (int i = blockIdx.x * blockDim.x + threadIdx.x; i < N_EDGES;
         i += gridDim.x * blockDim.x) {
        int dst = load_idx(ei, is64, (long long)N_EDGES + i);
        int pos = atomicAdd(&g_cursor[dst], 1);
        g_perm[pos] = i;
    }
}

// ---------------- launch 4 (PROFILED): A build, float4 LDS, grid-stride -----
__global__ void __launch_bounds__(128) k_abuild(const float* __restrict__ x,
                                                const void* __restrict__ ei,
                                                const float* __restrict__ ea,
                                                const float* __restrict__ w1,
                                                const float* __restrict__ b1) {
    int tid = threadIdx.x;
    int is64 = detect64(ei);

    // packed w1 pairs: w1r2[k] = (w1[2k][tid], w1[2k+1][tid]) — loaded once
    unsigned long long w1r2[8];
#pragma unroll
    for (int k = 0; k < 8; k++)
        w1r2[k] = pack2(w1[(2 * k) * HIDDEN + tid], w1[(2 * k + 1) * HIDDEN + tid]);
    float b1v = b1[tid];

    __shared__ int s_src[ECHUNK];
    __shared__ int s_e[ECHUNK];
    __shared__ __align__(16) float4 s_ea[ECHUNK][4];   // 8 KB
    __shared__ __align__(16) float4 s_xj[ECHUNK][8];   // 16 KB

    for (int n = blockIdx.x; n < N_NODES; n += ABLK) {
        int start = g_off[n], end = g_off[n + 1];
        int d = end - start;

        unsigned long long acc2[16];
#pragma unroll
        for (int m = 0; m < 16; m++) acc2[m] = 0ull;
        float xs = 0.f;

        for (int base = 0; base < d; base += ECHUNK) {
            int cnt = min(d - base, ECHUNK);
            __syncthreads();
            for (int j = tid; j < cnt; j += 128) {
                int e = g_perm[start + base + j];
                s_e[j] = e;
                s_src[j] = load_idx(ei, is64, e);
            }
            __syncthreads();
            for (int idx = tid; idx < cnt * 4; idx += 128) {
                int j = idx >> 2, q = idx & 3;
                s_ea[j][q] = ((const float4*)(ea + (size_t)s_e[j] * EDGE_DIM))[q];
            }
            for (int idx = tid; idx < cnt * 8; idx += 128) {
                int j = idx >> 3, q = idx & 7;
                s_xj[j][q] = ((const float4*)(x + (size_t)s_src[j] * IN_C))[q];
            }
            __syncthreads();

            for (int j = 0; j < cnt; j++) {
                // MLP: 4x LDS.128 (ea) + 8 fma2 against register w1 pairs
                float4 e0 = s_ea[j][0], e1 = s_ea[j][1];
                float4 e2 = s_ea[j][2], e3 = s_ea[j][3];
                unsigned long long h2 = mul2(pack2(e0.x, e0.y), w1r2[0]);
                fma2(h2, pack2(e0.z, e0.w), w1r2[1]);
                fma2(h2, pack2(e1.x, e1.y), w1r2[2]);
                fma2(h2, pack2(e1.z, e1.w), w1r2[3]);
                fma2(h2, pack2(e2.x, e2.y), w1r2[4]);
                fma2(h2, pack2(e2.z, e2.w), w1r2[5]);
                fma2(h2, pack2(e3.x, e3.y), w1r2[6]);
                fma2(h2, pack2(e3.z, e3.w), w1r2[7]);
                float hlo, hhi;
                unpack2(h2, hlo, hhi);
                float he = fmaxf(hlo + hhi + b1v, 0.f);
                unsigned long long he2 = pack2(he, he);

                // rank-1 update: 8x LDS.128 (x row) + 16 fma2
#pragma unroll
                for (int q = 0; q < 8; q++) {
                    float4 xv = s_xj[j][q];
                    fma2(acc2[2 * q], he2, pack2(xv.x, xv.y));
                    fma2(acc2[2 * q + 1], he2, pack2(xv.z, xv.w));
                }
                if (tid < IN_C) xs += ((const float*)s_xj)[j * 32 + tid];
            }
        }

        // unpack, split to bf16 hi/lo, pack, store 16 u32 per plane
        uint32_t ph[16], pl[16];
#pragma unroll
        for (int m = 0; m < 16; m++) {
            float a0, a1;
            unpack2(acc2[m], a0, a1);
            __nv_bfloat16 h0, l0, h1, l1;
            split_bf(a0, h0, l0);
            split_bf(a1, h1, l1);
            ph[m] = pack_bf(h0, h1);
            pl[m] = pack_bf(l0, l1);
        }
        uint4* aph = (uint4*)(g_Ah + (size_t)n * A_U32 + tid * 16);
        uint4* apl = (uint4*)(g_Al + (size_t)n * A_U32 + tid * 16);
#pragma unroll
        for (int q = 0; q < 4; q++) {
            aph[q] = make_uint4(ph[4 * q], ph[4 * q + 1], ph[4 * q + 2],
                                ph[4 * q + 3]);
            apl[q] = make_uint4(pl[4 * q], pl[4 * q + 1], pl[4 * q + 2],
                                pl[4 * q + 3]);
        }
        if (tid < IN_C) g_xsum[n * IN_C + tid] = xs;
    }
}

// ---------------- launch 5: GEMM, double-buffered smem, 1 bar/kt ------------
__global__ void __launch_bounds__(256) k_gemm(const float* __restrict__ x,
                                              const float* __restrict__ b2,
                                              const float* __restrict__ rw,
                                              const float* __restrict__ cb) {
    extern __shared__ __align__(16) unsigned char DYN[];
    __nv_bfloat16* A_hi = (__nv_bfloat16*)DYN;              // [2][128*40]
    __nv_bfloat16* A_lo = (__nv_bfloat16*)(DYN + 20480);    // [2][128*40]
    __nv_bfloat16* Wt_hi = (__nv_bfloat16*)(DYN + 40960);   // [2][32*40]
    __nv_bfloat16* Wt_lo = (__nv_bfloat16*)(DYN + 46080);   // [2][32*40]
    float* C_s = (float*)DYN;   // 16 KB alias, used after the mainloop
    __shared__ float B2s[1024], RWs[1024], cbs[32];

    int tid = threadIdx.x;
    int warp = tid >> 5, lane = tid & 31;
    int gi = lane >> 2, tq = lane & 3;
    int rowbase = blockIdx.x * BM;

#pragma unroll
    for (int q = 0; q < 4; q++) {
        int id = tid + q * 256;
        B2s[id] = b2[id];
        RWs[id] = rw[id];
    }
    if (tid < 32) cbs[tid] = cb[tid];

    float c[4][4];
#pragma unroll
    for (int j = 0; j < 4; j++)
#pragma unroll
        for (int r = 0; r < 4; r++) c[j][r] = 0.f;

    int lrow = tid >> 1, half = tid & 1;
    bool rowok = (rowbase + lrow) < N_NODES;
    const uint4* ahsrc =
        (const uint4*)(g_Ah + (size_t)(rowbase + lrow) * A_U32) + half * 2;
    const uint4* alsrc =
        (const uint4*)(g_Al + (size_t)(rowbase + lrow) * A_U32) + half * 2;

    uint4 vah[2], val[2];
    uint32_t wrh[2], wrl[2];

    // ---- prologue: load kt=0, store into buffer 0 ----
#pragma unroll
    for (int q = 0; q < 2; q++) {
        vah[q] = rowok ? ahsrc[q] : make_uint4(0, 0, 0, 0);
        val[q] = rowok ? alsrc[q] : make_uint4(0, 0, 0, 0);
    }
#pragma unroll
    for (int q = 0; q < 2; q++) {
        int id = tid + q * 256;
        wrh[q] = g_w2h[id];
        wrl[q] = g_w2l[id];
    }
    {
        uint4* dh = (uint4*)((uint32_t*)A_hi + lrow * 20 + half * 8);
        uint4* dl = (uint4*)((uint32_t*)A_lo + lrow * 20 + half * 8);
        dh[0] = vah[0]; dh[1] = vah[1];
        dl[0] = val[0]; dl[1] = val[1];
#pragma unroll
        for (int q = 0; q < 2; q++) {
            int id = tid + q * 256;
            int n = id >> 4, kp = id & 15;
            ((uint32_t*)Wt_hi)[n * 20 + kp] = wrh[q];
            ((uint32_t*)Wt_lo)[n * 20 + kp] = wrl[q];
        }
    }
    __syncthreads();

    for (int kt = 0; kt < NKT; kt++) {
        int cur = kt & 1, nxt = cur ^ 1;
        int ktn = kt + 1;
        bool more = ktn < NKT;
        // ---- prefetch kt+1 into registers (overlaps the MMAs below) ----
        if (more) {
#pragma unroll
            for (int q = 0; q < 2; q++) {
                vah[q] = rowok ? ahsrc[ktn * 4 + q] : make_uint4(0, 0, 0, 0);
                val[q] = rowok ? alsrc[ktn * 4 + q] : make_uint4(0, 0, 0, 0);
            }
#pragma unroll
            for (int q = 0; q < 2; q++) {
                int id = tid + q * 256;
                wrh[q] = g_w2h[ktn * 512 + id];
                wrl[q] = g_w2l[ktn * 512 + id];
            }
        }

        // ---- MMAs for kt from buffer cur ----
        int rb = warp * 16;
        const __nv_bfloat16* Ahc = A_hi + cur * 5120;
        const __nv_bfloat16* Alc = A_lo + cur * 5120;
        const __nv_bfloat16* Whc = Wt_hi + cur * 1280;
        const __nv_bfloat16* Wlc = Wt_lo + cur * 1280;
#pragma unroll
        for (int kk = 0; kk < BK; kk += 16) {
            const __nv_bfloat16* ah = &Ahc[(rb + gi) * ASTR + kk + 2 * tq];
            const __nv_bfloat16* al = &Alc[(rb + gi) * ASTR + kk + 2 * tq];
            uint32_t a0h = lds_u32(ah), a1h = lds_u32(ah + 8 * ASTR);
            uint32_t a2h = lds_u32(ah + 8), a3h = lds_u32(ah + 8 * ASTR + 8);
            uint32_t a0l = lds_u32(al), a1l = lds_u32(al + 8 * ASTR);
            uint32_t a2l = lds_u32(al + 8), a3l = lds_u32(al + 8 * ASTR + 8);
#pragma unroll
            for (int j = 0; j < 4; j++) {
                const __nv_bfloat16* bh = &Whc[(j * 8 + gi) * WSTR + kk + 2 * tq];
                const __nv_bfloat16* bl = &Wlc[(j * 8 + gi) * WSTR + kk + 2 * tq];
                uint32_t b0h = lds_u32(bh), b1h = lds_u32(bh + 8);
                uint32_t b0l = lds_u32(bl), b1l = lds_u32(bl + 8);
                mma16816(c[j], a0h, a1h, a2h, a3h, b0h, b1h);
                mma16816(c[j], a0h, a1h, a2h, a3h, b0l, b1l);
                mma16816(c[j], a0l, a1l, a2l, a3l, b0h, b1h);
            }
        }

        // ---- store kt+1 into buffer nxt (no WAR: MMAs read cur) ----
        if (more) {
            uint4* dh = (uint4*)((uint32_t*)A_hi + nxt * 2560 + lrow * 20 + half * 8);
            uint4* dl = (uint4*)((uint32_t*)A_lo + nxt * 2560 + lrow * 20 + half * 8);
            dh[0] = vah[0]; dh[1] = vah[1];
            dl[0] = val[0]; dl[1] = val[1];
#pragma unroll
            for (int q = 0; q < 2; q++) {
                int id = tid + q * 256;
                int n = id >> 4, kp = id & 15;
                ((uint32_t*)Wt_hi)[nxt * 640 + n * 20 + kp] = wrh[q];
                ((uint32_t*)Wt_lo)[nxt * 640 + n * 20 + kp] = wrl[q];
            }
        }
        __syncthreads();
    }

    // ---- dump accumulators to shared (aliases A buffers) ----
    {
        int rb = warp * 16;
#pragma unroll
        for (int j = 0; j < 4; j++) {
            int col = j * 8 + 2 * tq;
            C_s[(rb + gi) * 32 + col] = c[j][0];
            C_s[(rb + gi) * 32 + col + 1] = c[j][1];
            C_s[(rb + gi + 8) * 32 + col] = c[j][2];
            C_s[(rb + gi + 8) * 32 + col + 1] = c[j][3];
        }
    }
    __syncthreads();

    // ---- epilogue: mean, b2 term, root term, conv bias ----
    {
        int row = tid >> 1, ch = tid & 1;
        int mg = rowbase + row;
        if (mg < N_NODES) {
            float cnt = (float)(g_off[mg + 1] - g_off[mg]);
            float inv = 1.f / fmaxf(cnt, 1.f);
            const float4* xsp = (const float4*)(g_xsum + (size_t)mg * IN_C);
            const float4* xp = (const float4*)(x + (size_t)mg * IN_C);
            float eacc[16], racc[16];
#pragma unroll
            for (int cjj = 0; cjj < 16; cjj++) { eacc[cjj] = 0.f; racc[cjj] = 0.f; }
#pragma unroll
            for (int i4 = 0; i4 < 8; i4++) {
                float4 xsv = xsp[i4];
                float4 xvv = xp[i4];
                float sv[4] = {xsv.x, xsv.y, xsv.z, xsv.w};
                float vv[4] = {xvv.x, xvv.y, xvv.z, xvv.w};
#pragma unroll
                for (int ii = 0; ii < 4; ii++) {
                    int i = i4 * 4 + ii;
#pragma unroll
                    for (int cjj = 0; cjj < 16; cjj++) {
                        int col = ch * 16 + cjj;
                        eacc[cjj] += sv[ii] * B2s[i * 32 + col];
                        racc[cjj] += vv[ii] * RWs[i * 32 + col];
                    }
                }
            }
#pragma unroll
            for (int cjj = 0; cjj < 16; cjj++) {
                int col = ch * 16 + cjj;
                g_h[(size_t)mg * 32 + col] =
                    (C_s[row * 32 + col] + eacc[cjj]) * inv + racc[cjj] + cbs[col];
            }
        }
    }
}

// ---------------- BatchNorm statistics (deterministic, no atomics) ----------
__global__ void k_bnstats() {
    int tid = threadIdx.x;  // 256
    int c = tid & 31, g = tid >> 5;
    double s = 0.0, s2 = 0.0;
    for (int row = blockIdx.x * 8 + g; row < N_NODES; row += gridDim.x * 8) {
        float v = g_h[(size_t)row * 32 + c];
        s += (double)v;
        s2 += (double)v * (double)v;
    }
    __shared__ double sh[256], sh2[256];
    sh[tid] = s; sh2[tid] = s2;
    __syncthreads();
    for (int off = 128; off >= 32; off >>= 1) {
        if (tid < off) { sh[tid] += sh[tid + off]; sh2[tid] += sh2[tid + off]; }
        __syncthreads();
    }
    if (tid < 32) {
        g_psum[blockIdx.x][tid] = sh[tid];
        g_psq[blockIdx.x][tid] = sh2[tid];
    }
}

__global__ void k_bnfin(const float* __restrict__ gamma,
                        const float* __restrict__ beta) {
    int c = threadIdx.x;
    if (c < OUT_C) {
        double s = 0.0, s2 = 0.0;
        for (int b = 0; b < BN_BLOCKS; b++) {
            s += g_psum[b][c];
            s2 += g_psq[b][c];
        }
        double mu = s / (double)N_NODES;
        double var = s2 / (double)N_NODES - mu * mu;
        float rstd = (float)rsqrt(var + (double)BN_EPS);
        float sc = rstd * gamma[c];
        g_scale[c] = sc;
        g_shift[c] = beta[c] - (float)mu * sc;
    }
}

// ---------------- output: x + relu(BN(h)) ------------------------------------
__global__ void k_out(const float* __restrict__ x, float* __restrict__ out) {
    int i = blockIdx.x * blockDim.x + threadIdx.x;
    const int total = N_NODES * OUT_C / 4;
    if (i < total) {
        float4 xv = ((const float4*)x)[i];
        float4 hv = ((const float4*)g_h)[i];
        int c = (i & 7) * 4;
        float4 o;
        o.x = xv.x + fmaxf(hv.x * g_scale[c + 0] + g_shift[c + 0], 0.f);
        o.y = xv.y + fmaxf(hv.y * g_scale[c + 1] + g_shift[c + 1], 0.f);
        o.z = xv.z + fmaxf(hv.z * g_scale[c + 2] + g_shift[c + 2], 0.f);
        o.w = xv.w + fmaxf(hv.w * g_scale[c + 3] + g_shift[c + 3], 0.f);
        ((float4*)out)[i] = o;
    }
}

// ---------------- launch -----------------------------------------------------
extern "C" void kernel_launch(void* const* d_in, const int* in_sizes, int n_in,
                              void* d_out, int out_size) {
    const float* x   = (const float*)d_in[0];
    const void*  ei  = d_in[1];               // int32 or int64, self-detected
    const float* ea  = (const float*)d_in[2];
    const float* w1  = (const float*)d_in[3];
    const float* b1  = (const float*)d_in[4];
    const float* w2  = (const float*)d_in[5];
    const float* b2  = (const float*)d_in[6];
    const float* rw  = (const float*)d_in[7];
    const float* cb  = (const float*)d_in[8];
    const float* gam = (const float*)d_in[9];
    const float* bet = (const float*)d_in[10];
    float* out = (float*)d_out;

    cudaFuncSetAttribute(k_gemm, cudaFuncAttributeMaxDynamicSharedMemorySize,
                         GEMM_DYN);

    k_hist<<<512, 256>>>(ei, w2);             // launch 1
    k_scan<<<1, 1024>>>();                    // launch 2
    k_scatter<<<512, 256>>>(ei);              // launch 3
    k_abuild<<<ABLK, 128>>>(x, ei, ea, w1, b1);      // launch 4 (profiled)
    k_gemm<<<(N_NODES + BM - 1) / BM, 256, GEMM_DYN>>>(x, b2, rw, cb);
    k_bnstats<<<BN_BLOCKS, 256>>>();
    k_bnfin<<<1, 32>>>(gam, bet);
    k_out<<<(N_NODES * OUT_C / 4 + 255) / 256, 256>>>(x, out);
}

// round 9
// speedup vs baseline: 1.0791x; 1.0791x over previous
#include <cuda_runtime.h>
#include <cuda_bf16.h>
#include <cstdint>

#define N_NODES 50000
#define N_EDGES 400000
#define IN_C 32
#define OUT_C 32
#define EDGE_DIM 16
#define HIDDEN 128
#define BN_EPS 1e-5f

#define A_COLS (HIDDEN * IN_C)   // 4096
#define A_U32 (A_COLS / 2)       // 2048 packed u32 per node per plane
#define BN_BLOCKS 232

// GEMM tiling
#define BM 128
#define BK 32
#define NKT (A_COLS / BK)  // 128
#define ASTR 40
#define WSTR 40

// abuild chunking
#define ECHUNK 128

// ---------------- static device scratch (no allocations allowed) ------------
__device__ uint32_t g_Ah[(size_t)N_NODES * A_U32];     // 410 MB (bf16 hi pairs)
__device__ uint32_t g_Al[(size_t)N_NODES * A_U32];     // 410 MB (bf16 lo pairs)
__device__ uint32_t g_w2h[128 * 512];                  // W2 hi plane [kt][n][kp]
__device__ uint32_t g_w2l[128 * 512];
__device__ float g_xsum[(size_t)N_NODES * IN_C];
__device__ float g_h[(size_t)N_NODES * OUT_C];
__device__ int   g_hist[N_NODES];   // zero at module load; re-zeroed by k_scan
__device__ int   g_off[N_NODES + 1];
__device__ int   g_cursor[N_NODES];
__device__ int   g_perm[N_EDGES];
__device__ double g_psum[BN_BLOCKS][OUT_C];
__device__ double g_psq[BN_BLOCKS][OUT_C];
__device__ float g_scale[OUT_C];
__device__ float g_shift[OUT_C];

// ---------------- helpers ----------------------------------------------------
__device__ __forceinline__ void split_bf(float v, __nv_bfloat16& h,
                                         __nv_bfloat16& l) {
    h = __float2bfloat16_rn(v);
    l = __float2bfloat16_rn(v - __bfloat162float(h));
}

__device__ __forceinline__ uint32_t pack_bf(__nv_bfloat16 a, __nv_bfloat16 b) {
    __nv_bfloat162 p;
    p.x = a; p.y = b;
    return *reinterpret_cast<uint32_t*>(&p);
}

__device__ __forceinline__ uint32_t lds_u32(const __nv_bfloat16* p) {
    return *reinterpret_cast<const uint32_t*>(p);
}

__device__ __forceinline__ void mma16816(float c[4], uint32_t a0, uint32_t a1,
                                         uint32_t a2, uint32_t a3, uint32_t b0,
                                         uint32_t b1) {
    asm volatile(
        "mma.sync.aligned.m16n8k16.row.col.f32.bf16.bf16.f32 "
        "{%0,%1,%2,%3}, {%4,%5,%6,%7}, {%8,%9}, {%0,%1,%2,%3};"
        : "+f"(c[0]), "+f"(c[1]), "+f"(c[2]), "+f"(c[3])
        : "r"(a0), "r"(a1), "r"(a2), "r"(a3), "r"(b0), "r"(b1));
}

// packed f32x2 ops (sm_100+)
__device__ __forceinline__ unsigned long long pack2(float a, float b) {
    unsigned long long r;
    asm("mov.b64 %0, {%1, %2};" : "=l"(r) : "f"(a), "f"(b));
    return r;
}
__device__ __forceinline__ void unpack2(unsigned long long v, float& a, float& b) {
    asm("mov.b64 {%0, %1}, %2;" : "=f"(a), "=f"(b) : "l"(v));
}
__device__ __forceinline__ void fma2(unsigned long long& d, unsigned long long a,
                                     unsigned long long b) {
    asm("fma.rn.f32x2 %0, %1, %2, %0;" : "+l"(d) : "l"(a), "l"(b));
}
__device__ __forceinline__ unsigned long long mul2(unsigned long long a,
                                                   unsigned long long b) {
    unsigned long long r;
    asm("mul.rn.f32x2 %0, %1, %2;" : "=l"(r) : "l"(a), "l"(b));
    return r;
}

// self-detecting edge-index load (int32 vs int64 buffer layout)
__device__ __forceinline__ int detect64(const void* ei) {
    const int* p = (const int*)ei;
    return (p[1] == 0) & (p[3] == 0) & (p[5] == 0) & (p[7] == 0);
}
__device__ __forceinline__ int load_idx(const void* ei, int is64, long long elem) {
    int v = is64 ? (int)((const long long*)ei)[elem] : ((const int*)ei)[elem];
    return min(max(v, 0), N_NODES - 1);
}

// ---------------- launch 1: histogram over dst + W2 pre-split ----------------
__global__ void k_hist(const void* __restrict__ ei, const float* __restrict__ w2) {
    int is64 = detect64(ei);
    for (int i = blockIdx.x * blockDim.x + threadIdx.x; i < N_EDGES;
         i += gridDim.x * blockDim.x) {
        int dst = load_idx(ei, is64, (long long)N_EDGES + i);
        atomicAdd(&g_hist[dst], 1);
    }
    for (int id = blockIdx.x * blockDim.x + threadIdx.x; id < 128 * 512;
         id += gridDim.x * blockDim.x) {
        int kt = id >> 9, r = id & 511;
        int n = r >> 4, kp = r & 15;
        int k0 = kt * 32 + 2 * kp;
        float v0 = w2[(size_t)k0 * 32 + n];
        float v1 = w2[(size_t)(k0 + 1) * 32 + n];
        __nv_bfloat16 h0, l0, h1, l1;
        split_bf(v0, h0, l0);
        split_bf(v1, h1, l1);
        g_w2h[id] = pack_bf(h0, h1);
        g_w2l[id] = pack_bf(l0, l1);
    }
}

// ---------------- launch 2: single-block scan (also re-zeros g_hist) --------
__device__ __forceinline__ int block_excl_scan1024(int v, int* ws) {
    int tid = threadIdx.x;
    int lane = tid & 31, wid = tid >> 5;
    int incl = v;
#pragma unroll
    for (int o = 1; o < 32; o <<= 1) {
        int nv = __shfl_up_sync(0xffffffffu, incl, o);
        if (lane >= o) incl += nv;
    }
    if (lane == 31) ws[wid] = incl;
    __syncthreads();
    if (wid == 0) {
        int wv = ws[lane];
#pragma unroll
        for (int o = 1; o < 32; o <<= 1) {
            int nv = __shfl_up_sync(0xffffffffu, wv, o);
            if (lane >= o) wv += nv;
        }
        ws[lane] = wv;
    }
    __syncthreads();
    int base = (wid > 0) ? ws[wid - 1] : 0;
    return base + incl - v;
}

__global__ void __launch_bounds__(1024) k_scan() {
    __shared__ int ws[32];
    __shared__ int s_carry;
    int tid = threadIdx.x;
    if (tid == 0) s_carry = 0;
    __syncthreads();
    for (int base = 0; base < N_NODES; base += 1024) {
        int idx = base + tid;
        int v = (idx < N_NODES) ? g_hist[idx] : 0;
        int ex = block_excl_scan1024(v, ws);
        int c = s_carry;
        if (idx < N_NODES) {
            g_off[idx] = c + ex;
            g_cursor[idx] = c + ex;
            g_hist[idx] = 0;
        }
        __syncthreads();
        if (tid == 1023) s_carry = c + ex + v;
        __syncthreads();
    }
    if (tid == 0) g_off[N_NODES] = N_EDGES;
}

// ---------------- launch 3: scatter edge ids grouped by dst -----------------
__global__ void k_scatter(const void* __restrict__ ei) {
    int is64 = detect64(ei);
    for (int i = blockIdx.x * blockDim.x + threadIdx.x; i < N_EDGES;
         i += gridDim.x * blockDim.x) {
        int dst = load_idx(ei, is64, (long long)N_EDGES + i);
        int pos = atomicAdd(&g_cursor[dst], 1);
        g_perm[pos] = i;
    }
}

// ---------------- launch 4 (PROFILED): A build, occupancy-capped ------------
// block = one node, 128 threads (h = tid). Inner loop: broadcast LDS.64 +
// dual-lane FFMA2; MLP as two independent 4-deep chains.
__global__ void __launch_bounds__(128, 6) k_abuild(const float* __restrict__ x,
                                                   const void* __restrict__ ei,
                                                   const float* __restrict__ ea,
                                                   const float* __restrict__ w1,
                                                   const float* __restrict__ b1) {
    int n = blockIdx.x;
    int tid = threadIdx.x;
    int is64 = detect64(ei);
    int start = g_off[n], end = g_off[n + 1];
    int d = end - start;

    // packed w1 pairs: w1r2[k] = (w1[2k][tid], w1[2k+1][tid])
    unsigned long long w1r2[8];
#pragma unroll
    for (int k = 0; k < 8; k++)
        w1r2[k] = pack2(w1[(2 * k) * HIDDEN + tid], w1[(2 * k + 1) * HIDDEN + tid]);
    float b1v = b1[tid];

    __shared__ int s_src[ECHUNK];
    __shared__ int s_e[ECHUNK];
    __shared__ __align__(16) float4 s_ea[ECHUNK][4];   // 8 KB
    __shared__ __align__(16) float4 s_xj[ECHUNK][8];   // 16 KB

    unsigned long long acc2[16];
#pragma unroll
    for (int m = 0; m < 16; m++) acc2[m] = 0ull;
    float xs = 0.f;

    for (int base = 0; base < d; base += ECHUNK) {
        int cnt = min(d - base, ECHUNK);
        __syncthreads();
        for (int j = tid; j < cnt; j += 128) {
            int e = g_perm[start + base + j];
            s_e[j] = e;
            s_src[j] = load_idx(ei, is64, e);
        }
        __syncthreads();
        for (int idx = tid; idx < cnt * 4; idx += 128) {
            int j = idx >> 2, q = idx & 3;
            s_ea[j][q] = ((const float4*)(ea + (size_t)s_e[j] * EDGE_DIM))[q];
        }
        for (int idx = tid; idx < cnt * 8; idx += 128) {
            int j = idx >> 3, q = idx & 7;
            s_xj[j][q] = ((const float4*)(x + (size_t)s_src[j] * IN_C))[q];
        }
        __syncthreads();

        for (int j = 0; j < cnt; j++) {
            // MLP: 8 broadcast LDS.64 + two independent 4-deep fma2 chains
            const unsigned long long* eap =
                (const unsigned long long*)&s_ea[j][0];
            unsigned long long h2a = mul2(eap[0], w1r2[0]);
            unsigned long long h2b = mul2(eap[1], w1r2[1]);
            fma2(h2a, eap[2], w1r2[2]);
            fma2(h2b, eap[3], w1r2[3]);
            fma2(h2a, eap[4], w1r2[4]);
            fma2(h2b, eap[5], w1r2[5]);
            fma2(h2a, eap[6], w1r2[6]);
            fma2(h2b, eap[7], w1r2[7]);
            float alo, ahi, blo, bhi;
            unpack2(h2a, alo, ahi);
            unpack2(h2b, blo, bhi);
            float he = fmaxf((alo + blo) + (ahi + bhi) + b1v, 0.f);
            unsigned long long he2 = pack2(he, he);

            // rank-1 update: 16 broadcast LDS.64 + 16 fma2 (independent accs)
            const unsigned long long* xp2 =
                (const unsigned long long*)&s_xj[j][0];
#pragma unroll
            for (int m = 0; m < 16; m++) fma2(acc2[m], he2, xp2[m]);

            if (tid < IN_C) xs += ((const float*)s_xj)[j * 32 + tid];
        }
    }

    // unpack, split to bf16 hi/lo, pack, store 16 u32 per plane
    uint32_t ph[16], pl[16];
#pragma unroll
    for (int m = 0; m < 16; m++) {
        float a0, a1;
        unpack2(acc2[m], a0, a1);
        __nv_bfloat16 h0, l0, h1, l1;
        split_bf(a0, h0, l0);
        split_bf(a1, h1, l1);
        ph[m] = pack_bf(h0, h1);
        pl[m] = pack_bf(l0, l1);
    }
    uint4* aph = (uint4*)(g_Ah + (size_t)n * A_U32 + tid * 16);
    uint4* apl = (uint4*)(g_Al + (size_t)n * A_U32 + tid * 16);
#pragma unroll
    for (int q = 0; q < 4; q++) {
        aph[q] = make_uint4(ph[4 * q], ph[4 * q + 1], ph[4 * q + 2], ph[4 * q + 3]);
        apl[q] = make_uint4(pl[4 * q], pl[4 * q + 1], pl[4 * q + 2], pl[4 * q + 3]);
    }
    if (tid < IN_C) g_xsum[n * IN_C + tid] = xs;
}

// ---------------- launch 5: main GEMM on tensor cores (R7 exact) ------------
__global__ void __launch_bounds__(256) k_gemm(const float* __restrict__ x,
                                              const float* __restrict__ b2,
                                              const float* __restrict__ rw,
                                              const float* __restrict__ cb) {
    __shared__ __align__(16) unsigned char SMEM[25600];
    __nv_bfloat16* A_hi = (__nv_bfloat16*)SMEM;
    __nv_bfloat16* A_lo = (__nv_bfloat16*)(SMEM + 10240);
    __nv_bfloat16* Wt_hi = (__nv_bfloat16*)(SMEM + 20480);
    __nv_bfloat16* Wt_lo = (__nv_bfloat16*)(SMEM + 23040);
    float* C_s = (float*)SMEM;
    __shared__ float B2s[1024], RWs[1024], cbs[32];

    int tid = threadIdx.x;
    int warp = tid >> 5, lane = tid & 31;
    int gi = lane >> 2, tq = lane & 3;
    int rowbase = blockIdx.x * BM;

#pragma unroll
    for (int q = 0; q < 4; q++) {
        int id = tid + q * 256;
        B2s[id] = b2[id];
        RWs[id] = rw[id];
    }
    if (tid < 32) cbs[tid] = cb[tid];

    float c[4][4];
#pragma unroll
    for (int j = 0; j < 4; j++)
#pragma unroll
        for (int r = 0; r < 4; r++) c[j][r] = 0.f;

    int lrow = tid >> 1, half = tid & 1;
    bool rowok = (rowbase + lrow) < N_NODES;
    const uint4* ahsrc =
        (const uint4*)(g_Ah + (size_t)(rowbase + lrow) * A_U32) + half * 2;
    const uint4* alsrc =
        (const uint4*)(g_Al + (size_t)(rowbase + lrow) * A_U32) + half * 2;

    uint4 vah[2], val[2];
    uint32_t wrh[2], wrl[2];

#pragma unroll
    for (int q = 0; q < 2; q++) {
        vah[q] = rowok ? ahsrc[q] : make_uint4(0, 0, 0, 0);
        val[q] = rowok ? alsrc[q] : make_uint4(0, 0, 0, 0);
    }
#pragma unroll
    for (int q = 0; q < 2; q++) {
        int id = tid + q * 256;
        wrh[q] = g_w2h[id];
        wrl[q] = g_w2l[id];
    }
    {
        uint4* dh = (uint4*)((uint32_t*)A_hi + lrow * 20 + half * 8);
        uint4* dl = (uint4*)((uint32_t*)A_lo + lrow * 20 + half * 8);
        dh[0] = vah[0]; dh[1] = vah[1];
        dl[0] = val[0]; dl[1] = val[1];
#pragma unroll
        for (int q = 0; q < 2; q++) {
            int id = tid + q * 256;
            int n = id >> 4, kp = id & 15;
            ((uint32_t*)Wt_hi)[n * 20 + kp] = wrh[q];
            ((uint32_t*)Wt_lo)[n * 20 + kp] = wrl[q];
        }
    }
    __syncthreads();

    for (int kt = 0; kt < NKT; kt++) {
        int ktn = (kt + 1 < NKT) ? kt + 1 : kt;
#pragma unroll
        for (int q = 0; q < 2; q++) {
            vah[q] = rowok ? ahsrc[ktn * 4 + q] : make_uint4(0, 0, 0, 0);
            val[q] = rowok ? alsrc[ktn * 4 + q] : make_uint4(0, 0, 0, 0);
        }
#pragma unroll
        for (int q = 0; q < 2; q++) {
            int id = tid + q * 256;
            wrh[q] = g_w2h[ktn * 512 + id];
            wrl[q] = g_w2l[ktn * 512 + id];
        }

        int rb = warp * 16;
#pragma unroll
        for (int kk = 0; kk < BK; kk += 16) {
            const __nv_bfloat16* ah = &A_hi[(rb + gi) * ASTR + kk + 2 * tq];
            const __nv_bfloat16* al = &A_lo[(rb + gi) * ASTR + kk + 2 * tq];
            uint32_t a0h = lds_u32(ah), a1h = lds_u32(ah + 8 * ASTR);
            uint32_t a2h = lds_u32(ah + 8), a3h = lds_u32(ah + 8 * ASTR + 8);
            uint32_t a0l = lds_u32(al), a1l = lds_u32(al + 8 * ASTR);
            uint32_t a2l = lds_u32(al + 8), a3l = lds_u32(al + 8 * ASTR + 8);
#pragma unroll
            for (int j = 0; j < 4; j++) {
                const __nv_bfloat16* bh = &Wt_hi[(j * 8 + gi) * WSTR + kk + 2 * tq];
                const __nv_bfloat16* bl = &Wt_lo[(j * 8 + gi) * WSTR + kk + 2 * tq];
                uint32_t b0h = lds_u32(bh), b1h = lds_u32(bh + 8);
                uint32_t b0l = lds_u32(bl), b1l = lds_u32(bl + 8);
                mma16816(c[j], a0h, a1h, a2h, a3h, b0h, b1h);
                mma16816(c[j], a0h, a1h, a2h, a3h, b0l, b1l);
                mma16816(c[j], a0l, a1l, a2l, a3l, b0h, b1h);
            }
        }
        __syncthreads();

        if (kt + 1 < NKT) {
            uint4* dh = (uint4*)((uint32_t*)A_hi + lrow * 20 + half * 8);
            uint4* dl = (uint4*)((uint32_t*)A_lo + lrow * 20 + half * 8);
            dh[0] = vah[0]; dh[1] = vah[1];
            dl[0] = val[0]; dl[1] = val[1];
#pragma unroll
            for (int q = 0; q < 2; q++) {
                int id = tid + q * 256;
                int n = id >> 4, kp = id & 15;
                ((uint32_t*)Wt_hi)[n * 20 + kp] = wrh[q];
                ((uint32_t*)Wt_lo)[n * 20 + kp] = wrl[q];
            }
        }
        __syncthreads();
    }

    {
        int rb = warp * 16;
#pragma unroll
        for (int j = 0; j < 4; j++) {
            int col = j * 8 + 2 * tq;
            C_s[(rb + gi) * 32 + col] = c[j][0];
            C_s[(rb + gi) * 32 + col + 1] = c[j][1];
            C_s[(rb + gi + 8) * 32 + col] = c[j][2];
            C_s[(rb + gi + 8) * 32 + col + 1] = c[j][3];
        }
    }
    __syncthreads();

    {
        int row = tid >> 1, ch = tid & 1;
        int mg = rowbase + row;
        if (mg < N_NODES) {
            float cnt = (float)(g_off[mg + 1] - g_off[mg]);
            float inv = 1.f / fmaxf(cnt, 1.f);
            const float4* xsp = (const float4*)(g_xsum + (size_t)mg * IN_C);
            const float4* xp = (const float4*)(x + (size_t)mg * IN_C);
            float eacc[16], racc[16];
#pragma unroll
            for (int cjj = 0; cjj < 16; cjj++) { eacc[cjj] = 0.f; racc[cjj] = 0.f; }
#pragma unroll
            for (int i4 = 0; i4 < 8; i4++) {
                float4 xsv = xsp[i4];
                float4 xvv = xp[i4];
                float sv[4] = {xsv.x, xsv.y, xsv.z, xsv.w};
                float vv[4] = {xvv.x, xvv.y, xvv.z, xvv.w};
#pragma unroll
                for (int ii = 0; ii < 4; ii++) {
                    int i = i4 * 4 + ii;
#pragma unroll
                    for (int cjj = 0; cjj < 16; cjj++) {
                        int col = ch * 16 + cjj;
                        eacc[cjj] += sv[ii] * B2s[i * 32 + col];
                        racc[cjj] += vv[ii] * RWs[i * 32 + col];
                    }
                }
            }
#pragma unroll
            for (int cjj = 0; cjj < 16; cjj++) {
                int col = ch * 16 + cjj;
                g_h[(size_t)mg * 32 + col] =
                    (C_s[row * 32 + col] + eacc[cjj]) * inv + racc[cjj] + cbs[col];
            }
        }
    }
}

// ---------------- BatchNorm statistics (deterministic, no atomics) ----------
__global__ void k_bnstats() {
    int tid = threadIdx.x;  // 256
    int c = tid & 31, g = tid >> 5;
    double s = 0.0, s2 = 0.0;
    for (int row = blockIdx.x * 8 + g; row < N_NODES; row += gridDim.x * 8) {
        float v = g_h[(size_t)row * 32 + c];
        s += (double)v;
        s2 += (double)v * (double)v;
    }
    __shared__ double sh[256], sh2[256];
    sh[tid] = s; sh2[tid] = s2;
    __syncthreads();
    for (int off = 128; off >= 32; off >>= 1) {
        if (tid < off) { sh[tid] += sh[tid + off]; sh2[tid] += sh2[tid + off]; }
        __syncthreads();
    }
    if (tid < 32) {
        g_psum[blockIdx.x][tid] = sh[tid];
        g_psq[blockIdx.x][tid] = sh2[tid];
    }
}

__global__ void k_bnfin(const float* __restrict__ gamma,
                        const float* __restrict__ beta) {
    int c = threadIdx.x;
    if (c < OUT_C) {
        double s = 0.0, s2 = 0.0;
        for (int b = 0; b < BN_BLOCKS; b++) {
            s += g_psum[b][c];
            s2 += g_psq[b][c];
        }
        double mu = s / (double)N_NODES;
        double var = s2 / (double)N_NODES - mu * mu;
        float rstd = (float)rsqrt(var + (double)BN_EPS);
        float sc = rstd * gamma[c];
        g_scale[c] = sc;
        g_shift[c] = beta[c] - (float)mu * sc;
    }
}

// ---------------- output: x + relu(BN(h)) ------------------------------------
__global__ void k_out(const float* __restrict__ x, float* __restrict__ out) {
    int i = blockIdx.x * blockDim.x + threadIdx.x;
    const int total = N_NODES * OUT_C / 4;
    if (i < total) {
        float4 xv = ((const float4*)x)[i];
        float4 hv = ((const float4*)g_h)[i];
        int c = (i & 7) * 4;
        float4 o;
        o.x = xv.x + fmaxf(hv.x * g_scale[c + 0] + g_shift[c + 0], 0.f);
        o.y = xv.y + fmaxf(hv.y * g_scale[c + 1] + g_shift[c + 1], 0.f);
        o.z = xv.z + fmaxf(hv.z * g_scale[c + 2] + g_shift[c + 2], 0.f);
        o.w = xv.w + fmaxf(hv.w * g_scale[c + 3] + g_shift[c + 3], 0.f);
        ((float4*)out)[i] = o;
    }
}

// ---------------- launch -----------------------------------------------------
extern "C" void kernel_launch(void* const* d_in, const int* in_sizes, int n_in,
                              void* d_out, int out_size) {
    const float* x   = (const float*)d_in[0];
    const void*  ei  = d_in[1];               // int32 or int64, self-detected
    const float* ea  = (const float*)d_in[2];
    const float* w1  = (const float*)d_in[3];
    const float* b1  = (const float*)d_in[4];
    const float* w2  = (const float*)d_in[5];
    const float* b2  = (const float*)d_in[6];
    const float* rw  = (const float*)d_in[7];
    const float* cb  = (const float*)d_in[8];
    const float* gam = (const float*)d_in[9];
    const float* bet = (const float*)d_in[10];
    float* out = (float*)d_out;

    k_hist<<<512, 256>>>(ei, w2);             // launch 1
    k_scan<<<1, 1024>>>();                    // launch 2
    k_scatter<<<512, 256>>>(ei);              // launch 3
    k_abuild<<<N_NODES, 128>>>(x, ei, ea, w1, b1);   // launch 4 (profiled)
    k_gemm<<<(N_NODES + BM - 1) / BM, 256>>>(x, b2, rw, cb);
    k_bnstats<<<BN_BLOCKS, 256>>>();
    k_bnfin<<<1, 32>>>(gam, bet);
    k_out<<<(N_NODES * OUT_C / 4 + 255) / 256, 256>>>(x, out);
}

// round 10
// speedup vs baseline: 1.1051x; 1.0241x over previous
#include <cuda_runtime.h>
#include <cuda_bf16.h>
#include <cstdint>

#define N_NODES 50000
#define N_EDGES 400000
#define IN_C 32
#define OUT_C 32
#define EDGE_DIM 16
#define HIDDEN 128
#define BN_EPS 1e-5f

#define A_COLS (HIDDEN * IN_C)   // 4096
#define A_U32 (A_COLS / 2)       // 2048 packed u32 per node per plane
#define BN_BLOCKS 232

// GEMM tiling
#define BM 128
#define BK 32
#define NKT (A_COLS / BK)  // 128
#define ASTR 40
#define WSTR 40

// abuild: node-group blocking
#define GNODES 16
#define ECAP 128
#define NGROUPS ((N_NODES + GNODES - 1) / GNODES)   // 3125

// ---------------- static device scratch (no allocations allowed) ------------
__device__ uint32_t g_Ah[(size_t)N_NODES * A_U32];     // 410 MB (bf16 hi pairs)
__device__ uint32_t g_Al[(size_t)N_NODES * A_U32];     // 410 MB (bf16 lo pairs)
__device__ uint32_t g_w2h[128 * 512];                  // W2 hi plane [kt][n][kp]
__device__ uint32_t g_w2l[128 * 512];
__device__ float g_xsum[(size_t)N_NODES * IN_C];
__device__ float g_h[(size_t)N_NODES * OUT_C];
__device__ int   g_hist[N_NODES];   // zero at module load; re-zeroed by k_scan
__device__ int   g_off[N_NODES + 1];
__device__ int   g_cursor[N_NODES];
__device__ int   g_perm[N_EDGES];
__device__ double g_psum[BN_BLOCKS][OUT_C];
__device__ double g_psq[BN_BLOCKS][OUT_C];
__device__ float g_scale[OUT_C];
__device__ float g_shift[OUT_C];

// ---------------- helpers ----------------------------------------------------
__device__ __forceinline__ void split_bf(float v, __nv_bfloat16& h,
                                         __nv_bfloat16& l) {
    h = __float2bfloat16_rn(v);
    l = __float2bfloat16_rn(v - __bfloat162float(h));
}

__device__ __forceinline__ uint32_t pack_bf(__nv_bfloat16 a, __nv_bfloat16 b) {
    __nv_bfloat162 p;
    p.x = a; p.y = b;
    return *reinterpret_cast<uint32_t*>(&p);
}

__device__ __forceinline__ uint32_t lds_u32(const __nv_bfloat16* p) {
    return *reinterpret_cast<const uint32_t*>(p);
}

__device__ __forceinline__ void mma16816(float c[4], uint32_t a0, uint32_t a1,
                                         uint32_t a2, uint32_t a3, uint32_t b0,
                                         uint32_t b1) {
    asm volatile(
        "mma.sync.aligned.m16n8k16.row.col.f32.bf16.bf16.f32 "
        "{%0,%1,%2,%3}, {%4,%5,%6,%7}, {%8,%9}, {%0,%1,%2,%3};"
        : "+f"(c[0]), "+f"(c[1]), "+f"(c[2]), "+f"(c[3])
        : "r"(a0), "r"(a1), "r"(a2), "r"(a3), "r"(b0), "r"(b1));
}

// packed f32x2 ops (sm_100+)
__device__ __forceinline__ unsigned long long pack2(float a, float b) {
    unsigned long long r;
    asm("mov.b64 %0, {%1, %2};" : "=l"(r) : "f"(a), "f"(b));
    return r;
}
__device__ __forceinline__ void unpack2(unsigned long long v, float& a, float& b) {
    asm("mov.b64 {%0, %1}, %2;" : "=f"(a), "=f"(b) : "l"(v));
}
__device__ __forceinline__ void fma2(unsigned long long& d, unsigned long long a,
                                     unsigned long long b) {
    asm("fma.rn.f32x2 %0, %1, %2, %0;" : "+l"(d) : "l"(a), "l"(b));
}
__device__ __forceinline__ unsigned long long mul2(unsigned long long a,
                                                   unsigned long long b) {
    unsigned long long r;
    asm("mul.rn.f32x2 %0, %1, %2;" : "=l"(r) : "l"(a), "l"(b));
    return r;
}

// self-detecting edge-index load (int32 vs int64 buffer layout)
__device__ __forceinline__ int detect64(const void* ei) {
    const int* p = (const int*)ei;
    return (p[1] == 0) & (p[3] == 0) & (p[5] == 0) & (p[7] == 0);
}
__device__ __forceinline__ int load_idx(const void* ei, int is64, long long elem) {
    int v = is64 ? (int)((const long long*)ei)[elem] : ((const int*)ei)[elem];
    return min(max(v, 0), N_NODES - 1);
}

// ---------------- launch 1: histogram over dst + W2 pre-split ----------------
__global__ void k_hist(const void* __restrict__ ei, const float* __restrict__ w2) {
    int is64 = detect64(ei);
    for (int i = blockIdx.x * blockDim.x + threadIdx.x; i < N_EDGES;
         i += gridDim.x * blockDim.x) {
        int dst = load_idx(ei, is64, (long long)N_EDGES + i);
        atomicAdd(&g_hist[dst], 1);
    }
    for (int id = blockIdx.x * blockDim.x + threadIdx.x; id < 128 * 512;
         id += gridDim.x * blockDim.x) {
        int kt = id >> 9, r = id & 511;
        int n = r >> 4, kp = r & 15;
        int k0 = kt * 32 + 2 * kp;
        float v0 = w2[(size_t)k0 * 32 + n];
        float v1 = w2[(size_t)(k0 + 1) * 32 + n];
        __nv_bfloat16 h0, l0, h1, l1;
        split_bf(v0, h0, l0);
        split_bf(v1, h1, l1);
        g_w2h[id] = pack_bf(h0, h1);
        g_w2l[id] = pack_bf(l0, l1);
    }
}

// ---------------- launch 2: single-block scan (also re-zeros g_hist) --------
__device__ __forceinline__ int block_excl_scan1024(int v, int* ws) {
    int tid = threadIdx.x;
    int lane = tid & 31, wid = tid >> 5;
    int incl = v;
#pragma unroll
    for (int o = 1; o < 32; o <<= 1) {
        int nv = __shfl_up_sync(0xffffffffu, incl, o);
        if (lane >= o) incl += nv;
    }
    if (lane == 31) ws[wid] = incl;
    __syncthreads();
    if (wid == 0) {
        int wv = ws[lane];
#pragma unroll
        for (int o = 1; o < 32; o <<= 1) {
            int nv = __shfl_up_sync(0xffffffffu, wv, o);
            if (lane >= o) wv += nv;
        }
        ws[lane] = wv;
    }
    __syncthreads();
    int base = (wid > 0) ? ws[wid - 1] : 0;
    return base + incl - v;
}

__global__ void __launch_bounds__(1024) k_scan() {
    __shared__ int ws[32];
    __shared__ int s_carry;
    int tid = threadIdx.x;
    if (tid == 0) s_carry = 0;
    __syncthreads();
    for (int base = 0; base < N_NODES; base += 1024) {
        int idx = base + tid;
        int v = (idx < N_NODES) ? g_hist[idx] : 0;
        int ex = block_excl_scan1024(v, ws);
        int c = s_carry;
        if (idx < N_NODES) {
            g_off[idx] = c + ex;
            g_cursor[idx] = c + ex;
            g_hist[idx] = 0;
        }
        __syncthreads();
        if (tid == 1023) s_carry = c + ex + v;
        __syncthreads();
    }
    if (tid == 0) g_off[N_NODES] = N_EDGES;
}

// ---------------- launch 3: scatter edge ids grouped by dst -----------------
__global__ void k_scatter(const void* __restrict__ ei) {
    int is64 = detect64(ei);
    for (int i = blockIdx.x * blockDim.x + threadIdx.x; i < N_EDGES;
         i += gridDim.x * blockDim.x) {
        int dst = load_idx(ei, is64, (long long)N_EDGES + i);
        int pos = atomicAdd(&g_cursor[dst], 1);
        g_perm[pos] = i;
    }
}

// ---------------- launch 4 (PROFILED): A build, 16-node group blocking ------
__device__ __forceinline__ void stage_edges(int estart, int cnt, int tid,
                                            int is64, const void* ei,
                                            const float* ea, const float* x,
                                            int* s_e, int* s_src,
                                            float4 (*s_ea)[4],
                                            float4 (*s_xj)[8]) {
    __syncthreads();   // guards WAR on smem from previous window
    for (int j = tid; j < cnt; j += 128) {
        int e = g_perm[estart + j];
        s_e[j] = e;
        s_src[j] = load_idx(ei, is64, e);
    }
    __syncthreads();
    for (int idx = tid; idx < cnt * 4; idx += 128) {
        int j = idx >> 2, q = idx & 3;
        s_ea[j][q] = ((const float4*)(ea + (size_t)s_e[j] * EDGE_DIM))[q];
    }
    for (int idx = tid; idx < cnt * 8; idx += 128) {
        int j = idx >> 3, q = idx & 7;
        s_xj[j][q] = ((const float4*)(x + (size_t)s_src[j] * IN_C))[q];
    }
    __syncthreads();
}

__device__ __forceinline__ void accum_edge(int j, int tid,
                                           const unsigned long long* w1r2,
                                           float b1v,
                                           unsigned long long* acc2, float& xs,
                                           float4 (*s_ea)[4],
                                           float4 (*s_xj)[8]) {
    // MLP: 8 broadcast LDS.64 + two independent 4-deep fma2 chains
    const unsigned long long* eap = (const unsigned long long*)&s_ea[j][0];
    unsigned long long h2a = mul2(eap[0], w1r2[0]);
    unsigned long long h2b = mul2(eap[1], w1r2[1]);
    fma2(h2a, eap[2], w1r2[2]);
    fma2(h2b, eap[3], w1r2[3]);
    fma2(h2a, eap[4], w1r2[4]);
    fma2(h2b, eap[5], w1r2[5]);
    fma2(h2a, eap[6], w1r2[6]);
    fma2(h2b, eap[7], w1r2[7]);
    float alo, ahi, blo, bhi;
    unpack2(h2a, alo, ahi);
    unpack2(h2b, blo, bhi);
    float he = fmaxf((alo + blo) + (ahi + bhi) + b1v, 0.f);
    unsigned long long he2 = pack2(he, he);

    const unsigned long long* xp2 = (const unsigned long long*)&s_xj[j][0];
#pragma unroll
    for (int m = 0; m < 16; m++) fma2(acc2[m], he2, xp2[m]);

    if (tid < IN_C) xs += ((const float*)s_xj)[j * 32 + tid];
}

__device__ __forceinline__ void store_node(int n, int tid,
                                           const unsigned long long* acc2,
                                           float xs) {
    uint32_t ph[16], pl[16];
#pragma unroll
    for (int m = 0; m < 16; m++) {
        float a0, a1;
        unpack2(acc2[m], a0, a1);
        __nv_bfloat16 h0, l0, h1, l1;
        split_bf(a0, h0, l0);
        split_bf(a1, h1, l1);
        ph[m] = pack_bf(h0, h1);
        pl[m] = pack_bf(l0, l1);
    }
    uint4* aph = (uint4*)(g_Ah + (size_t)n * A_U32 + tid * 16);
    uint4* apl = (uint4*)(g_Al + (size_t)n * A_U32 + tid * 16);
#pragma unroll
    for (int q = 0; q < 4; q++) {
        aph[q] = make_uint4(ph[4 * q], ph[4 * q + 1], ph[4 * q + 2], ph[4 * q + 3]);
        apl[q] = make_uint4(pl[4 * q], pl[4 * q + 1], pl[4 * q + 2], pl[4 * q + 3]);
    }
    if (tid < IN_C) g_xsum[n * IN_C + tid] = xs;
}

__global__ void __launch_bounds__(128, 6) k_abuild(const float* __restrict__ x,
                                                   const void* __restrict__ ei,
                                                   const float* __restrict__ ea,
                                                   const float* __restrict__ w1,
                                                   const float* __restrict__ b1) {
    int tid = threadIdx.x;
    int is64 = detect64(ei);
    int n0 = blockIdx.x * GNODES;
    int nlocal = min(GNODES, N_NODES - n0);

    // packed w1 pairs (once per block of 16 nodes)
    unsigned long long w1r2[8];
#pragma unroll
    for (int k = 0; k < 8; k++)
        w1r2[k] = pack2(w1[(2 * k) * HIDDEN + tid], w1[(2 * k + 1) * HIDDEN + tid]);
    float b1v = b1[tid];

    __shared__ int s_off[GNODES + 1];
    __shared__ int s_src[ECAP];
    __shared__ int s_e[ECAP];
    __shared__ __align__(16) float4 s_ea[ECAP][4];   // 8 KB
    __shared__ __align__(16) float4 s_xj[ECAP][8];   // 16 KB

    if (tid <= nlocal) s_off[tid] = g_off[n0 + tid];
    __syncthreads();

    int pnode = 0;
    while (pnode < nlocal) {
        int estart = s_off[pnode];
        // extend window over whole nodes while it fits in ECAP
        int qnode = pnode;
        while (qnode < nlocal && s_off[qnode + 1] - estart <= ECAP) qnode++;

        if (qnode > pnode) {
            // common path: window of whole nodes
            int cnt = s_off[qnode] - estart;
            stage_edges(estart, cnt, tid, is64, ei, ea, x, s_e, s_src, s_ea, s_xj);
            for (int nn = pnode; nn < qnode; nn++) {
                unsigned long long acc2[16];
#pragma unroll
                for (int m = 0; m < 16; m++) acc2[m] = 0ull;
                float xs = 0.f;
                int ls = s_off[nn] - estart, le = s_off[nn + 1] - estart;
                for (int j = ls; j < le; j++)
                    accum_edge(j, tid, w1r2, b1v, acc2, xs, s_ea, s_xj);
                store_node(n0 + nn, tid, acc2, xs);
            }
            pnode = qnode;
        } else {
            // rare path: single node with degree > ECAP, chunked
            int d = s_off[pnode + 1] - estart;
            unsigned long long acc2[16];
#pragma unroll
            for (int m = 0; m < 16; m++) acc2[m] = 0ull;
            float xs = 0.f;
            for (int b = 0; b < d; b += ECAP) {
                int cc = min(d - b, ECAP);
                stage_edges(estart + b, cc, tid, is64, ei, ea, x, s_e, s_src,
                            s_ea, s_xj);
                for (int j = 0; j < cc; j++)
                    accum_edge(j, tid, w1r2, b1v, acc2, xs, s_ea, s_xj);
            }
            store_node(n0 + pnode, tid, acc2, xs);
            pnode++;
        }
    }
}

// ---------------- launch 5: main GEMM on tensor cores (R7 exact) ------------
__global__ void __launch_bounds__(256) k_gemm(const float* __restrict__ x,
                                              const float* __restrict__ b2,
                                              const float* __restrict__ rw,
                                              const float* __restrict__ cb) {
    __shared__ __align__(16) unsigned char SMEM[25600];
    __nv_bfloat16* A_hi = (__nv_bfloat16*)SMEM;
    __nv_bfloat16* A_lo = (__nv_bfloat16*)(SMEM + 10240);
    __nv_bfloat16* Wt_hi = (__nv_bfloat16*)(SMEM + 20480);
    __nv_bfloat16* Wt_lo = (__nv_bfloat16*)(SMEM + 23040);
    float* C_s = (float*)SMEM;
    __shared__ float B2s[1024], RWs[1024], cbs[32];

    int tid = threadIdx.x;
    int warp = tid >> 5, lane = tid & 31;
    int gi = lane >> 2, tq = lane & 3;
    int rowbase = blockIdx.x * BM;

#pragma unroll
    for (int q = 0; q < 4; q++) {
        int id = tid + q * 256;
        B2s[id] = b2[id];
        RWs[id] = rw[id];
    }
    if (tid < 32) cbs[tid] = cb[tid];

    float c[4][4];
#pragma unroll
    for (int j = 0; j < 4; j++)
#pragma unroll
        for (int r = 0; r < 4; r++) c[j][r] = 0.f;

    int lrow = tid >> 1, half = tid & 1;
    bool rowok = (rowbase + lrow) < N_NODES;
    const uint4* ahsrc =
        (const uint4*)(g_Ah + (size_t)(rowbase + lrow) * A_U32) + half * 2;
    const uint4* alsrc =
        (const uint4*)(g_Al + (size_t)(rowbase + lrow) * A_U32) + half * 2;

    uint4 vah[2], val[2];
    uint32_t wrh[2], wrl[2];

#pragma unroll
    for (int q = 0; q < 2; q++) {
        vah[q] = rowok ? ahsrc[q] : make_uint4(0, 0, 0, 0);
        val[q] = rowok ? alsrc[q] : make_uint4(0, 0, 0, 0);
    }
#pragma unroll
    for (int q = 0; q < 2; q++) {
        int id = tid + q * 256;
        wrh[q] = g_w2h[id];
        wrl[q] = g_w2l[id];
    }
    {
        uint4* dh = (uint4*)((uint32_t*)A_hi + lrow * 20 + half * 8);
        uint4* dl = (uint4*)((uint32_t*)A_lo + lrow * 20 + half * 8);
        dh[0] = vah[0]; dh[1] = vah[1];
        dl[0] = val[0]; dl[1] = val[1];
#pragma unroll
        for (int q = 0; q < 2; q++) {
            int id = tid + q * 256;
            int n = id >> 4, kp = id & 15;
            ((uint32_t*)Wt_hi)[n * 20 + kp] = wrh[q];
            ((uint32_t*)Wt_lo)[n * 20 + kp] = wrl[q];
        }
    }
    __syncthreads();

    for (int kt = 0; kt < NKT; kt++) {
        int ktn = (kt + 1 < NKT) ? kt + 1 : kt;
#pragma unroll
        for (int q = 0; q < 2; q++) {
            vah[q] = rowok ? ahsrc[ktn * 4 + q] : make_uint4(0, 0, 0, 0);
            val[q] = rowok ? alsrc[ktn * 4 + q] : make_uint4(0, 0, 0, 0);
        }
#pragma unroll
        for (int q = 0; q < 2; q++) {
            int id = tid + q * 256;
            wrh[q] = g_w2h[ktn * 512 + id];
            wrl[q] = g_w2l[ktn * 512 + id];
        }

        int rb = warp * 16;
#pragma unroll
        for (int kk = 0; kk < BK; kk += 16) {
            const __nv_bfloat16* ah = &A_hi[(rb + gi) * ASTR + kk + 2 * tq];
            const __nv_bfloat16* al = &A_lo[(rb + gi) * ASTR + kk + 2 * tq];
            uint32_t a0h = lds_u32(ah), a1h = lds_u32(ah + 8 * ASTR);
            uint32_t a2h = lds_u32(ah + 8), a3h = lds_u32(ah + 8 * ASTR + 8);
            uint32_t a0l = lds_u32(al), a1l = lds_u32(al + 8 * ASTR);
            uint32_t a2l = lds_u32(al + 8), a3l = lds_u32(al + 8 * ASTR + 8);
#pragma unroll
            for (int j = 0; j < 4; j++) {
                const __nv_bfloat16* bh = &Wt_hi[(j * 8 + gi) * WSTR + kk + 2 * tq];
                const __nv_bfloat16* bl = &Wt_lo[(j * 8 + gi) * WSTR + kk + 2 * tq];
                uint32_t b0h = lds_u32(bh), b1h = lds_u32(bh + 8);
                uint32_t b0l = lds_u32(bl), b1l = lds_u32(bl + 8);
                mma16816(c[j], a0h, a1h, a2h, a3h, b0h, b1h);
                mma16816(c[j], a0h, a1h, a2h, a3h, b0l, b1l);
                mma16816(c[j], a0l, a1l, a2l, a3l, b0h, b1h);
            }
        }
        __syncthreads();

        if (kt + 1 < NKT) {
            uint4* dh = (uint4*)((uint32_t*)A_hi + lrow * 20 + half * 8);
            uint4* dl = (uint4*)((uint32_t*)A_lo + lrow * 20 + half * 8);
            dh[0] = vah[0]; dh[1] = vah[1];
            dl[0] = val[0]; dl[1] = val[1];
#pragma unroll
            for (int q = 0; q < 2; q++) {
                int id = tid + q * 256;
                int n = id >> 4, kp = id & 15;
                ((uint32_t*)Wt_hi)[n * 20 + kp] = wrh[q];
                ((uint32_t*)Wt_lo)[n * 20 + kp] = wrl[q];
            }
        }
        __syncthreads();
    }

    {
        int rb = warp * 16;
#pragma unroll
        for (int j = 0; j < 4; j++) {
            int col = j * 8 + 2 * tq;
            C_s[(rb + gi) * 32 + col] = c[j][0];
            C_s[(rb + gi) * 32 + col + 1] = c[j][1];
            C_s[(rb + gi + 8) * 32 + col] = c[j][2];
            C_s[(rb + gi + 8) * 32 + col + 1] = c[j][3];
        }
    }
    __syncthreads();

    {
        int row = tid >> 1, ch = tid & 1;
        int mg = rowbase + row;
        if (mg < N_NODES) {
            float cnt = (float)(g_off[mg + 1] - g_off[mg]);
            float inv = 1.f / fmaxf(cnt, 1.f);
            const float4* xsp = (const float4*)(g_xsum + (size_t)mg * IN_C);
            const float4* xp = (const float4*)(x + (size_t)mg * IN_C);
            float eacc[16], racc[16];
#pragma unroll
            for (int cjj = 0; cjj < 16; cjj++) { eacc[cjj] = 0.f; racc[cjj] = 0.f; }
#pragma unroll
            for (int i4 = 0; i4 < 8; i4++) {
                float4 xsv = xsp[i4];
                float4 xvv = xp[i4];
                float sv[4] = {xsv.x, xsv.y, xsv.z, xsv.w};
                float vv[4] = {xvv.x, xvv.y, xvv.z, xvv.w};
#pragma unroll
                for (int ii = 0; ii < 4; ii++) {
                    int i = i4 * 4 + ii;
#pragma unroll
                    for (int cjj = 0; cjj < 16; cjj++) {
                        int col = ch * 16 + cjj;
                        eacc[cjj] += sv[ii] * B2s[i * 32 + col];
                        racc[cjj] += vv[ii] * RWs[i * 32 + col];
                    }
                }
            }
#pragma unroll
            for (int cjj = 0; cjj < 16; cjj++) {
                int col = ch * 16 + cjj;
                g_h[(size_t)mg * 32 + col] =
                    (C_s[row * 32 + col] + eacc[cjj]) * inv + racc[cjj] + cbs[col];
            }
        }
    }
}

// ---------------- BatchNorm statistics (deterministic, no atomics) ----------
__global__ void k_bnstats() {
    int tid = threadIdx.x;  // 256
    int c = tid & 31, g = tid >> 5;
    double s = 0.0, s2 = 0.0;
    for (int row = blockIdx.x * 8 + g; row < N_NODES; row += gridDim.x * 8) {
        float v = g_h[(size_t)row * 32 + c];
        s += (double)v;
        s2 += (double)v * (double)v;
    }
    __shared__ double sh[256], sh2[256];
    sh[tid] = s; sh2[tid] = s2;
    __syncthreads();
    for (int off = 128; off >= 32; off >>= 1) {
        if (tid < off) { sh[tid] += sh[tid + off]; sh2[tid] += sh2[tid + off]; }
        __syncthreads();
    }
    if (tid < 32) {
        g_psum[blockIdx.x][tid] = sh[tid];
        g_psq[blockIdx.x][tid] = sh2[tid];
    }
}

__global__ void k_bnfin(const float* __restrict__ gamma,
                        const float* __restrict__ beta) {
    int c = threadIdx.x;
    if (c < OUT_C) {
        double s = 0.0, s2 = 0.0;
        for (int b = 0; b < BN_BLOCKS; b++) {
            s += g_psum[b][c];
            s2 += g_psq[b][c];
        }
        double mu = s / (double)N_NODES;
        double var = s2 / (double)N_NODES - mu * mu;
        float rstd = (float)rsqrt(var + (double)BN_EPS);
        float sc = rstd * gamma[c];
        g_scale[c] = sc;
        g_shift[c] = beta[c] - (float)mu * sc;
    }
}

// ---------------- output: x + relu(BN(h)) ------------------------------------
__global__ void k_out(const float* __restrict__ x, float* __restrict__ out) {
    int i = blockIdx.x * blockDim.x + threadIdx.x;
    const int total = N_NODES * OUT_C / 4;
    if (i < total) {
        float4 xv = ((const float4*)x)[i];
        float4 hv = ((const float4*)g_h)[i];
        int c = (i & 7) * 4;
        float4 o;
        o.x = xv.x + fmaxf(hv.x * g_scale[c + 0] + g_shift[c + 0], 0.f);
        o.y = xv.y + fmaxf(hv.y * g_scale[c + 1] + g_shift[c + 1], 0.f);
        o.z = xv.z + fmaxf(hv.z * g_scale[c + 2] + g_shift[c + 2], 0.f);
        o.w = xv.w + fmaxf(hv.w * g_scale[c + 3] + g_shift[c + 3], 0.f);
        ((float4*)out)[i] = o;
    }
}

// ---------------- launch -----------------------------------------------------
extern "C" void kernel_launch(void* const* d_in, const int* in_sizes, int n_in,
                              void* d_out, int out_size) {
    const float* x   = (const float*)d_in[0];
    const void*  ei  = d_in[1];               // int32 or int64, self-detected
    const float* ea  = (const float*)d_in[2];
    const float* w1  = (const float*)d_in[3];
    const float* b1  = (const float*)d_in[4];
    const float* w2  = (const float*)d_in[5];
    const float* b2  = (const float*)d_in[6];
    const float* rw  = (const float*)d_in[7];
    const float* cb  = (const float*)d_in[8];
    const float* gam = (const float*)d_in[9];
    const float* bet = (const float*)d_in[10];
    float* out = (float*)d_out;

    k_hist<<<512, 256>>>(ei, w2);             // launch 1
    k_scan<<<1, 1024>>>();                    // launch 2
    k_scatter<<<512, 256>>>(ei);              // launch 3
    k_abuild<<<NGROUPS, 128>>>(x, ei, ea, w1, b1);   // launch 4 (profiled)
    k_gemm<<<(N_NODES + BM - 1) / BM, 256>>>(x, b2, rw, cb);
    k_bnstats<<<BN_BLOCKS, 256>>>();
    k_bnfin<<<1, 32>>>(gam, bet);
    k_out<<<(N_NODES * OUT_C / 4 + 255) / 256, 256>>>(x, out);
}

// round 11
// speedup vs baseline: 1.1569x; 1.0470x over previous
#include <cuda_runtime.h>
#include <cuda_bf16.h>
#include <cstdint>

#define N_NODES 50000
#define N_EDGES 400000
#define IN_C 32
#define OUT_C 32
#define EDGE_DIM 16
#define HIDDEN 128
#define BN_EPS 1e-5f

#define A_COLS (HIDDEN * IN_C)   // 4096
#define A_U32 (A_COLS / 2)       // 2048 packed u32 per node per plane
#define BN_BLOCKS 232

// GEMM tiling
#define BM 128
#define BK 32
#define NKT (A_COLS / BK)  // 128
#define ASTR 40
#define WSTR 40

// abuild: node-group blocking
#define GNODES 16
#define ECAP 128
#define NGROUPS ((N_NODES + GNODES - 1) / GNODES)   // 3125

// ---------------- static device scratch (no allocations allowed) ------------
__device__ uint32_t g_Ah[(size_t)N_NODES * A_U32];     // 410 MB (bf16 hi pairs)
__device__ uint32_t g_Al[(size_t)N_NODES * A_U32];     // 410 MB (bf16 lo pairs)
__device__ uint32_t g_w2h[128 * 512];                  // W2 hi plane [kt][n][kp]
__device__ uint32_t g_w2l[128 * 512];
__device__ float g_xsum[(size_t)N_NODES * IN_C];
__device__ float g_h[(size_t)N_NODES * OUT_C];
__device__ int   g_hist[N_NODES];   // zero at module load; re-zeroed by k_scan
__device__ int   g_off[N_NODES + 1];
__device__ int   g_cursor[N_NODES];
__device__ int   g_perm[N_EDGES];
__device__ double g_psum[BN_BLOCKS][OUT_C];
__device__ double g_psq[BN_BLOCKS][OUT_C];
__device__ float g_scale[OUT_C];
__device__ float g_shift[OUT_C];

// ---------------- helpers ----------------------------------------------------
__device__ __forceinline__ void split_bf(float v, __nv_bfloat16& h,
                                         __nv_bfloat16& l) {
    h = __float2bfloat16_rn(v);
    l = __float2bfloat16_rn(v - __bfloat162float(h));
}

__device__ __forceinline__ uint32_t pack_bf(__nv_bfloat16 a, __nv_bfloat16 b) {
    __nv_bfloat162 p;
    p.x = a; p.y = b;
    return *reinterpret_cast<uint32_t*>(&p);
}

__device__ __forceinline__ uint32_t lds_u32(const __nv_bfloat16* p) {
    return *reinterpret_cast<const uint32_t*>(p);
}

__device__ __forceinline__ void mma16816(float c[4], uint32_t a0, uint32_t a1,
                                         uint32_t a2, uint32_t a3, uint32_t b0,
                                         uint32_t b1) {
    asm volatile(
        "mma.sync.aligned.m16n8k16.row.col.f32.bf16.bf16.f32 "
        "{%0,%1,%2,%3}, {%4,%5,%6,%7}, {%8,%9}, {%0,%1,%2,%3};"
        : "+f"(c[0]), "+f"(c[1]), "+f"(c[2]), "+f"(c[3])
        : "r"(a0), "r"(a1), "r"(a2), "r"(a3), "r"(b0), "r"(b1));
}

// packed f32x2 ops (sm_100+)
__device__ __forceinline__ unsigned long long pack2(float a, float b) {
    unsigned long long r;
    asm("mov.b64 %0, {%1, %2};" : "=l"(r) : "f"(a), "f"(b));
    return r;
}
__device__ __forceinline__ void unpack2(unsigned long long v, float& a, float& b) {
    asm("mov.b64 {%0, %1}, %2;" : "=f"(a), "=f"(b) : "l"(v));
}
__device__ __forceinline__ void fma2(unsigned long long& d, unsigned long long a,
                                     unsigned long long b) {
    asm("fma.rn.f32x2 %0, %1, %2, %0;" : "+l"(d) : "l"(a), "l"(b));
}
__device__ __forceinline__ unsigned long long mul2(unsigned long long a,
                                                   unsigned long long b) {
    unsigned long long r;
    asm("mul.rn.f32x2 %0, %1, %2;" : "=l"(r) : "l"(a), "l"(b));
    return r;
}

// self-detecting edge-index load (int32 vs int64 buffer layout)
__device__ __forceinline__ int detect64(const void* ei) {
    const int* p = (const int*)ei;
    return (p[1] == 0) & (p[3] == 0) & (p[5] == 0) & (p[7] == 0);
}
__device__ __forceinline__ int load_idx(const void* ei, int is64, long long elem) {
    int v = is64 ? (int)((const long long*)ei)[elem] : ((const int*)ei)[elem];
    return min(max(v, 0), N_NODES - 1);
}

// ---------------- launch 1: histogram over dst + W2 pre-split ----------------
__global__ void k_hist(const void* __restrict__ ei, const float* __restrict__ w2) {
    int is64 = detect64(ei);
    for (int i = blockIdx.x * blockDim.x + threadIdx.x; i < N_EDGES;
         i += gridDim.x * blockDim.x) {
        int dst = load_idx(ei, is64, (long long)N_EDGES + i);
        atomicAdd(&g_hist[dst], 1);
    }
    for (int id = blockIdx.x * blockDim.x + threadIdx.x; id < 128 * 512;
         id += gridDim.x * blockDim.x) {
        int kt = id >> 9, r = id & 511;
        int n = r >> 4, kp = r & 15;
        int k0 = kt * 32 + 2 * kp;
        float v0 = w2[(size_t)k0 * 32 + n];
        float v1 = w2[(size_t)(k0 + 1) * 32 + n];
        __nv_bfloat16 h0, l0, h1, l1;
        split_bf(v0, h0, l0);
        split_bf(v1, h1, l1);
        g_w2h[id] = pack_bf(h0, h1);
        g_w2l[id] = pack_bf(l0, l1);
    }
}

// ---------------- launch 2: single-block scan (also re-zeros g_hist) --------
__device__ __forceinline__ int block_excl_scan1024(int v, int* ws) {
    int tid = threadIdx.x;
    int lane = tid & 31, wid = tid >> 5;
    int incl = v;
#pragma unroll
    for (int o = 1; o < 32; o <<= 1) {
        int nv = __shfl_up_sync(0xffffffffu, incl, o);
        if (lane >= o) incl += nv;
    }
    if (lane == 31) ws[wid] = incl;
    __syncthreads();
    if (wid == 0) {
        int wv = ws[lane];
#pragma unroll
        for (int o = 1; o < 32; o <<= 1) {
            int nv = __shfl_up_sync(0xffffffffu, wv, o);
            if (lane >= o) wv += nv;
        }
        ws[lane] = wv;
    }
    __syncthreads();
    int base = (wid > 0) ? ws[wid - 1] : 0;
    return base + incl - v;
}

__global__ void __launch_bounds__(1024) k_scan() {
    __shared__ int ws[32];
    __shared__ int s_carry;
    int tid = threadIdx.x;
    if (tid == 0) s_carry = 0;
    __syncthreads();
    for (int base = 0; base < N_NODES; base += 1024) {
        int idx = base + tid;
        int v = (idx < N_NODES) ? g_hist[idx] : 0;
        int ex = block_excl_scan1024(v, ws);
        int c = s_carry;
        if (idx < N_NODES) {
            g_off[idx] = c + ex;
            g_cursor[idx] = c + ex;
            g_hist[idx] = 0;
        }
        __syncthreads();
        if (tid == 1023) s_carry = c + ex + v;
        __syncthreads();
    }
    if (tid == 0) g_off[N_NODES] = N_EDGES;
}

// ---------------- launch 3: scatter edge ids grouped by dst -----------------
__global__ void k_scatter(const void* __restrict__ ei) {
    int is64 = detect64(ei);
    for (int i = blockIdx.x * blockDim.x + threadIdx.x; i < N_EDGES;
         i += gridDim.x * blockDim.x) {
        int dst = load_idx(ei, is64, (long long)N_EDGES + i);
        int pos = atomicAdd(&g_cursor[dst], 1);
        g_perm[pos] = i;
    }
}

// ---------------- launch 4 (PROFILED): A build, LDS.128, group blocking -----
__device__ __forceinline__ void stage_edges(int estart, int cnt, int tid,
                                            int is64, const void* ei,
                                            const float* ea, const float* x,
                                            int* s_e, int* s_src,
                                            float4 (*s_ea)[4],
                                            float4 (*s_xj)[8]) {
    __syncthreads();   // guards WAR on smem from previous window
    for (int j = tid; j < cnt; j += 128) {
        int e = g_perm[estart + j];
        s_e[j] = e;
        s_src[j] = load_idx(ei, is64, e);
    }
    __syncthreads();
    for (int idx = tid; idx < cnt * 4; idx += 128) {
        int j = idx >> 2, q = idx & 3;
        s_ea[j][q] = ((const float4*)(ea + (size_t)s_e[j] * EDGE_DIM))[q];
    }
    for (int idx = tid; idx < cnt * 8; idx += 128) {
        int j = idx >> 3, q = idx & 7;
        s_xj[j][q] = ((const float4*)(x + (size_t)s_src[j] * IN_C))[q];
    }
    __syncthreads();
}

__device__ __forceinline__ void accum_edge(int j, int tid,
                                           const unsigned long long* w1r2,
                                           float b1v,
                                           unsigned long long* acc2, float& xs,
                                           float4 (*s_ea)[4],
                                           float4 (*s_xj)[8]) {
    // MLP: 4 broadcast LDS.128 + two independent 4-deep fma2 chains.
    // pack2 on .xy/.zw of a float4 is register-pair aliasing in SASS (free).
    float4 e0 = s_ea[j][0], e1 = s_ea[j][1], e2 = s_ea[j][2], e3 = s_ea[j][3];
    unsigned long long h2a = mul2(pack2(e0.x, e0.y), w1r2[0]);
    unsigned long long h2b = mul2(pack2(e0.z, e0.w), w1r2[1]);
    fma2(h2a, pack2(e1.x, e1.y), w1r2[2]);
    fma2(h2b, pack2(e1.z, e1.w), w1r2[3]);
    fma2(h2a, pack2(e2.x, e2.y), w1r2[4]);
    fma2(h2b, pack2(e2.z, e2.w), w1r2[5]);
    fma2(h2a, pack2(e3.x, e3.y), w1r2[6]);
    fma2(h2b, pack2(e3.z, e3.w), w1r2[7]);
    float alo, ahi, blo, bhi;
    unpack2(h2a, alo, ahi);
    unpack2(h2b, blo, bhi);
    float he = fmaxf((alo + blo) + (ahi + bhi) + b1v, 0.f);
    unsigned long long he2 = pack2(he, he);

    // rank-1 update: 8 broadcast LDS.128 + 16 fma2 (independent accumulators)
#pragma unroll
    for (int q = 0; q < 8; q++) {
        float4 xv = s_xj[j][q];
        fma2(acc2[2 * q], he2, pack2(xv.x, xv.y));
        fma2(acc2[2 * q + 1], he2, pack2(xv.z, xv.w));
    }

    if (tid < IN_C) xs += ((const float*)s_xj)[j * 32 + tid];
}

__device__ __forceinline__ void store_node(int n, int tid,
                                           const unsigned long long* acc2,
                                           float xs) {
    uint32_t ph[16], pl[16];
#pragma unroll
    for (int m = 0; m < 16; m++) {
        float a0, a1;
        unpack2(acc2[m], a0, a1);
        __nv_bfloat16 h0, l0, h1, l1;
        split_bf(a0, h0, l0);
        split_bf(a1, h1, l1);
        ph[m] = pack_bf(h0, h1);
        pl[m] = pack_bf(l0, l1);
    }
    uint4* aph = (uint4*)(g_Ah + (size_t)n * A_U32 + tid * 16);
    uint4* apl = (uint4*)(g_Al + (size_t)n * A_U32 + tid * 16);
#pragma unroll
    for (int q = 0; q < 4; q++) {
        aph[q] = make_uint4(ph[4 * q], ph[4 * q + 1], ph[4 * q + 2], ph[4 * q + 3]);
        apl[q] = make_uint4(pl[4 * q], pl[4 * q + 1], pl[4 * q + 2], pl[4 * q + 3]);
    }
    if (tid < IN_C) g_xsum[n * IN_C + tid] = xs;
}

__global__ void __launch_bounds__(128, 6) k_abuild(const float* __restrict__ x,
                                                   const void* __restrict__ ei,
                                                   const float* __restrict__ ea,
                                                   const float* __restrict__ w1,
                                                   const float* __restrict__ b1) {
    int tid = threadIdx.x;
    int is64 = detect64(ei);
    int n0 = blockIdx.x * GNODES;
    int nlocal = min(GNODES, N_NODES - n0);

    // packed w1 pairs (once per block of 16 nodes)
    unsigned long long w1r2[8];
#pragma unroll
    for (int k = 0; k < 8; k++)
        w1r2[k] = pack2(w1[(2 * k) * HIDDEN + tid], w1[(2 * k + 1) * HIDDEN + tid]);
    float b1v = b1[tid];

    __shared__ int s_off[GNODES + 1];
    __shared__ int s_src[ECAP];
    __shared__ int s_e[ECAP];
    __shared__ __align__(16) float4 s_ea[ECAP][4];   // 8 KB
    __shared__ __align__(16) float4 s_xj[ECAP][8];   // 16 KB

    if (tid <= nlocal) s_off[tid] = g_off[n0 + tid];
    __syncthreads();

    int pnode = 0;
    while (pnode < nlocal) {
        int estart = s_off[pnode];
        // extend window over whole nodes while it fits in ECAP
        int qnode = pnode;
        while (qnode < nlocal && s_off[qnode + 1] - estart <= ECAP) qnode++;

        if (qnode > pnode) {
            // common path: window of whole nodes
            int cnt = s_off[qnode] - estart;
            stage_edges(estart, cnt, tid, is64, ei, ea, x, s_e, s_src, s_ea, s_xj);
            for (int nn = pnode; nn < qnode; nn++) {
                unsigned long long acc2[16];
#pragma unroll
                for (int m = 0; m < 16; m++) acc2[m] = 0ull;
                float xs = 0.f;
                int ls = s_off[nn] - estart, le = s_off[nn + 1] - estart;
                for (int j = ls; j < le; j++)
                    accum_edge(j, tid, w1r2, b1v, acc2, xs, s_ea, s_xj);
                store_node(n0 + nn, tid, acc2, xs);
            }
            pnode = qnode;
        } else {
            // rare path: single node with degree > ECAP, chunked
            int d = s_off[pnode + 1] - estart;
            unsigned long long acc2[16];
#pragma unroll
            for (int m = 0; m < 16; m++) acc2[m] = 0ull;
            float xs = 0.f;
            for (int b = 0; b < d; b += ECAP) {
                int cc = min(d - b, ECAP);
                stage_edges(estart + b, cc, tid, is64, ei, ea, x, s_e, s_src,
                            s_ea, s_xj);
                for (int j = 0; j < cc; j++)
                    accum_edge(j, tid, w1r2, b1v, acc2, xs, s_ea, s_xj);
            }
            store_node(n0 + pnode, tid, acc2, xs);
            pnode++;
        }
    }
}

// ---------------- launch 5: main GEMM on tensor cores (R7 exact) ------------
__global__ void __launch_bounds__(256) k_gemm(const float* __restrict__ x,
                                              const float* __restrict__ b2,
                                              const float* __restrict__ rw,
                                              const float* __restrict__ cb) {
    __shared__ __align__(16) unsigned char SMEM[25600];
    __nv_bfloat16* A_hi = (__nv_bfloat16*)SMEM;
    __nv_bfloat16* A_lo = (__nv_bfloat16*)(SMEM + 10240);
    __nv_bfloat16* Wt_hi = (__nv_bfloat16*)(SMEM + 20480);
    __nv_bfloat16* Wt_lo = (__nv_bfloat16*)(SMEM + 23040);
    float* C_s = (float*)SMEM;
    __shared__ float B2s[1024], RWs[1024], cbs[32];

    int tid = threadIdx.x;
    int warp = tid >> 5, lane = tid & 31;
    int gi = lane >> 2, tq = lane & 3;
    int rowbase = blockIdx.x * BM;

#pragma unroll
    for (int q = 0; q < 4; q++) {
        int id = tid + q * 256;
        B2s[id] = b2[id];
        RWs[id] = rw[id];
    }
    if (tid < 32) cbs[tid] = cb[tid];

    float c[4][4];
#pragma unroll
    for (int j = 0; j < 4; j++)
#pragma unroll
        for (int r = 0; r < 4; r++) c[j][r] = 0.f;

    int lrow = tid >> 1, half = tid & 1;
    bool rowok = (rowbase + lrow) < N_NODES;
    const uint4* ahsrc =
        (const uint4*)(g_Ah + (size_t)(rowbase + lrow) * A_U32) + half * 2;
    const uint4* alsrc =
        (const uint4*)(g_Al + (size_t)(rowbase + lrow) * A_U32) + half * 2;

    uint4 vah[2], val[2];
    uint32_t wrh[2], wrl[2];

#pragma unroll
    for (int q = 0; q < 2; q++) {
        vah[q] = rowok ? ahsrc[q] : make_uint4(0, 0, 0, 0);
        val[q] = rowok ? alsrc[q] : make_uint4(0, 0, 0, 0);
    }
#pragma unroll
    for (int q = 0; q < 2; q++) {
        int id = tid + q * 256;
        wrh[q] = g_w2h[id];
        wrl[q] = g_w2l[id];
    }
    {
        uint4* dh = (uint4*)((uint32_t*)A_hi + lrow * 20 + half * 8);
        uint4* dl = (uint4*)((uint32_t*)A_lo + lrow * 20 + half * 8);
        dh[0] = vah[0]; dh[1] = vah[1];
        dl[0] = val[0]; dl[1] = val[1];
#pragma unroll
        for (int q = 0; q < 2; q++) {
            int id = tid + q * 256;
            int n = id >> 4, kp = id & 15;
            ((uint32_t*)Wt_hi)[n * 20 + kp] = wrh[q];
            ((uint32_t*)Wt_lo)[n * 20 + kp] = wrl[q];
        }
    }
    __syncthreads();

    for (int kt = 0; kt < NKT; kt++) {
        int ktn = (kt + 1 < NKT) ? kt + 1 : kt;
#pragma unroll
        for (int q = 0; q < 2; q++) {
            vah[q] = rowok ? ahsrc[ktn * 4 + q] : make_uint4(0, 0, 0, 0);
            val[q] = rowok ? alsrc[ktn * 4 + q] : make_uint4(0, 0, 0, 0);
        }
#pragma unroll
        for (int q = 0; q < 2; q++) {
            int id = tid + q * 256;
            wrh[q] = g_w2h[ktn * 512 + id];
            wrl[q] = g_w2l[ktn * 512 + id];
        }

        int rb = warp * 16;
#pragma unroll
        for (int kk = 0; kk < BK; kk += 16) {
            const __nv_bfloat16* ah = &A_hi[(rb + gi) * ASTR + kk + 2 * tq];
            const __nv_bfloat16* al = &A_lo[(rb + gi) * ASTR + kk + 2 * tq];
            uint32_t a0h = lds_u32(ah), a1h = lds_u32(ah + 8 * ASTR);
            uint32_t a2h = lds_u32(ah + 8), a3h = lds_u32(ah + 8 * ASTR + 8);
            uint32_t a0l = lds_u32(al), a1l = lds_u32(al + 8 * ASTR);
            uint32_t a2l = lds_u32(al + 8), a3l = lds_u32(al + 8 * ASTR + 8);
#pragma unroll
            for (int j = 0; j < 4; j++) {
                const __nv_bfloat16* bh = &Wt_hi[(j * 8 + gi) * WSTR + kk + 2 * tq];
                const __nv_bfloat16* bl = &Wt_lo[(j * 8 + gi) * WSTR + kk + 2 * tq];
                uint32_t b0h = lds_u32(bh), b1h = lds_u32(bh + 8);
                uint32_t b0l = lds_u32(bl), b1l = lds_u32(bl + 8);
                mma16816(c[j], a0h, a1h, a2h, a3h, b0h, b1h);
                mma16816(c[j], a0h, a1h, a2h, a3h, b0l, b1l);
                mma16816(c[j], a0l, a1l, a2l, a3l, b0h, b1h);
            }
        }
        __syncthreads();

        if (kt + 1 < NKT) {
            uint4* dh = (uint4*)((uint32_t*)A_hi + lrow * 20 + half * 8);
            uint4* dl = (uint4*)((uint32_t*)A_lo + lrow * 20 + half * 8);
            dh[0] = vah[0]; dh[1] = vah[1];
            dl[0] = val[0]; dl[1] = val[1];
#pragma unroll
            for (int q = 0; q < 2; q++) {
                int id = tid + q * 256;
                int n = id >> 4, kp = id & 15;
                ((uint32_t*)Wt_hi)[n * 20 + kp] = wrh[q];
                ((uint32_t*)Wt_lo)[n * 20 + kp] = wrl[q];
            }
        }
        __syncthreads();
    }

    {
        int rb = warp * 16;
#pragma unroll
        for (int j = 0; j < 4; j++) {
            int col = j * 8 + 2 * tq;
            C_s[(rb + gi) * 32 + col] = c[j][0];
            C_s[(rb + gi) * 32 + col + 1] = c[j][1];
            C_s[(rb + gi + 8) * 32 + col] = c[j][2];
            C_s[(rb + gi + 8) * 32 + col + 1] = c[j][3];
        }
    }
    __syncthreads();

    {
        int row = tid >> 1, ch = tid & 1;
        int mg = rowbase + row;
        if (mg < N_NODES) {
            float cnt = (float)(g_off[mg + 1] - g_off[mg]);
            float inv = 1.f / fmaxf(cnt, 1.f);
            const float4* xsp = (const float4*)(g_xsum + (size_t)mg * IN_C);
            const float4* xp = (const float4*)(x + (size_t)mg * IN_C);
            float eacc[16], racc[16];
#pragma unroll
            for (int cjj = 0; cjj < 16; cjj++) { eacc[cjj] = 0.f; racc[cjj] = 0.f; }
#pragma unroll
            for (int i4 = 0; i4 < 8; i4++) {
                float4 xsv = xsp[i4];
                float4 xvv = xp[i4];
                float sv[4] = {xsv.x, xsv.y, xsv.z, xsv.w};
                float vv[4] = {xvv.x, xvv.y, xvv.z, xvv.w};
#pragma unroll
                for (int ii = 0; ii < 4; ii++) {
                    int i = i4 * 4 + ii;
#pragma unroll
                    for (int cjj = 0; cjj < 16; cjj++) {
                        int col = ch * 16 + cjj;
                        eacc[cjj] += sv[ii] * B2s[i * 32 + col];
                        racc[cjj] += vv[ii] * RWs[i * 32 + col];
                    }
                }
            }
#pragma unroll
            for (int cjj = 0; cjj < 16; cjj++) {
                int col = ch * 16 + cjj;
                g_h[(size_t)mg * 32 + col] =
                    (C_s[row * 32 + col] + eacc[cjj]) * inv + racc[cjj] + cbs[col];
            }
        }
    }
}

// ---------------- BatchNorm statistics (deterministic, no atomics) ----------
__global__ void k_bnstats() {
    int tid = threadIdx.x;  // 256
    int c = tid & 31, g = tid >> 5;
    double s = 0.0, s2 = 0.0;
    for (int row = blockIdx.x * 8 + g; row < N_NODES; row += gridDim.x * 8) {
        float v = g_h[(size_t)row * 32 + c];
        s += (double)v;
        s2 += (double)v * (double)v;
    }
    __shared__ double sh[256], sh2[256];
    sh[tid] = s; sh2[tid] = s2;
    __syncthreads();
    for (int off = 128; off >= 32; off >>= 1) {
        if (tid < off) { sh[tid] += sh[tid + off]; sh2[tid] += sh2[tid + off]; }
        __syncthreads();
    }
    if (tid < 32) {
        g_psum[blockIdx.x][tid] = sh[tid];
        g_psq[blockIdx.x][tid] = sh2[tid];
    }
}

__global__ void k_bnfin(const float* __restrict__ gamma,
                        const float* __restrict__ beta) {
    int c = threadIdx.x;
    if (c < OUT_C) {
        double s = 0.0, s2 = 0.0;
        for (int b = 0; b < BN_BLOCKS; b++) {
            s += g_psum[b][c];
            s2 += g_psq[b][c];
        }
        double mu = s / (double)N_NODES;
        double var = s2 / (double)N_NODES - mu * mu;
        float rstd = (float)rsqrt(var + (double)BN_EPS);
        float sc = rstd * gamma[c];
        g_scale[c] = sc;
        g_shift[c] = beta[c] - (float)mu * sc;
    }
}

// ---------------- output: x + relu(BN(h)) ------------------------------------
__global__ void k_out(const float* __restrict__ x, float* __restrict__ out) {
    int i = blockIdx.x * blockDim.x + threadIdx.x;
    const int total = N_NODES * OUT_C / 4;
    if (i < total) {
        float4 xv = ((const float4*)x)[i];
        float4 hv = ((const float4*)g_h)[i];
        int c = (i & 7) * 4;
        float4 o;
        o.x = xv.x + fmaxf(hv.x * g_scale[c + 0] + g_shift[c + 0], 0.f);
        o.y = xv.y + fmaxf(hv.y * g_scale[c + 1] + g_shift[c + 1], 0.f);
        o.z = xv.z + fmaxf(hv.z * g_scale[c + 2] + g_shift[c + 2], 0.f);
        o.w = xv.w + fmaxf(hv.w * g_scale[c + 3] + g_shift[c + 3], 0.f);
        ((float4*)out)[i] = o;
    }
}

// ---------------- launch -----------------------------------------------------
extern "C" void kernel_launch(void* const* d_in, const int* in_sizes, int n_in,
                              void* d_out, int out_size) {
    const float* x   = (const float*)d_in[0];
    const void*  ei  = d_in[1];               // int32 or int64, self-detected
    const float* ea  = (const float*)d_in[2];
    const float* w1  = (const float*)d_in[3];
    const float* b1  = (const float*)d_in[4];
    const float* w2  = (const float*)d_in[5];
    const float* b2  = (const float*)d_in[6];
    const float* rw  = (const float*)d_in[7];
    const float* cb  = (const float*)d_in[8];
    const float* gam = (const float*)d_in[9];
    const float* bet = (const float*)d_in[10];
    float* out = (float*)d_out;

    k_hist<<<512, 256>>>(ei, w2);             // launch 1
    k_scan<<<1, 1024>>>();                    // launch 2
    k_scatter<<<512, 256>>>(ei);              // launch 3
    k_abuild<<<NGROUPS, 128>>>(x, ei, ea, w1, b1);   // launch 4 (profiled)
    k_gemm<<<(N_NODES + BM - 1) / BM, 256>>>(x, b2, rw, cb);
    k_bnstats<<<BN_BLOCKS, 256>>>();
    k_bnfin<<<1, 32>>>(gam, bet);
    k_out<<<(N_NODES * OUT_C / 4 + 255) / 256, 256>>>(x, out);
}